// round 3
// baseline (speedup 1.0000x reference)
#include <cuda_runtime.h>
#include <cstdint>

// Problem constants
#define S_LEN 1024
#define B_SZ  8
#define E_DIM 512
#define H_NUM 8
#define QHD   32
#define PHD   4
#define PDIM  192
#define IN_PROJ 544          // (32+32+4)*8
#define NPE   2047           // 2*S-1
#define NPE_PAD 2048

typedef unsigned long long u64;

// ---- packed f32x2 helpers (FFMA2: 2x fp32 FMA throughput, PTX-only) ----
__device__ __forceinline__ u64 pack2(float lo, float hi) {
    u64 r; asm("mov.b64 %0, {%1, %2};" : "=l"(r) : "f"(lo), "f"(hi)); return r;
}
__device__ __forceinline__ u64 pack2s(float v) {
    u64 r; asm("mov.b64 %0, {%1, %1};" : "=l"(r) : "f"(v)); return r;
}
__device__ __forceinline__ void fma2(u64& d, u64 a, u64 b) {
    asm("fma.rn.f32x2 %0, %1, %2, %0;" : "+l"(d) : "l"(a), "l"(b));
}
__device__ __forceinline__ float2 unpack2(u64 v) {
    float lo, hi; asm("mov.b64 {%0, %1}, %2;" : "=f"(lo), "=f"(hi) : "l"(v));
    return make_float2(lo, hi);
}

// ---------------- device scratch (no allocations allowed) ----------------
__device__ float g_Q[B_SZ * H_NUM * S_LEN * QHD];     // [b][h][s][d]
__device__ float g_K[B_SZ * H_NUM * QHD * S_LEN];     // [b][h][d][s] (transposed)
__device__ float g_P[B_SZ * H_NUM * S_LEN * PHD];     // [b][h][s][p]
__device__ float g_peT[H_NUM * PHD * NPE_PAD];        // [h][p][n]

// ---------------- kernel 1: pe = pos_emb @ linear_pos_w^T ----------------
// peT[h][p][n] = sum_d pos_emb[n][d] * lpw[h*4+p][d]
// block: (32 n) x (8 hp-groups of 4); weights broadcast per warp, pos_emb smem-tiled.
#define PE_NB 32
#define PE_PAD 193
#define PE_WPAD 34
#define PE_SMEM_BYTES ((PE_NB * PE_PAD + PDIM * PE_WPAD) * 4)
__global__ void __launch_bounds__(256) pe_kernel(const float* __restrict__ pos_emb,
                                                 const float* __restrict__ lpw) {
    extern __shared__ float psm[];
    float* pet = psm;                          // [32][193]
    float* wt  = psm + PE_NB * PE_PAD;         // [192][34] (transposed lpw)
    const int tid = threadIdx.y * 32 + threadIdx.x;
    const int n0 = blockIdx.x * PE_NB;

    for (int idx = tid; idx < PE_NB * (PDIM / 4); idx += 256) {
        int r = idx / (PDIM / 4), c = (idx % (PDIM / 4)) * 4;
        float4 v = make_float4(0.f, 0.f, 0.f, 0.f);
        if (n0 + r < NPE) v = *(const float4*)(pos_emb + (size_t)(n0 + r) * PDIM + c);
        pet[r * PE_PAD + c + 0] = v.x;
        pet[r * PE_PAD + c + 1] = v.y;
        pet[r * PE_PAD + c + 2] = v.z;
        pet[r * PE_PAD + c + 3] = v.w;
    }
    for (int idx = tid; idx < 32 * (PDIM / 4); idx += 256) {
        int r = idx / (PDIM / 4), c = (idx % (PDIM / 4)) * 4;
        float4 v = *(const float4*)(lpw + (size_t)r * PDIM + c);
        wt[(c + 0) * PE_WPAD + r] = v.x;
        wt[(c + 1) * PE_WPAD + r] = v.y;
        wt[(c + 2) * PE_WPAD + r] = v.z;
        wt[(c + 3) * PE_WPAD + r] = v.w;
    }
    __syncthreads();

    const int x = threadIdx.x;     // n_local
    const int y = threadIdx.y;     // hp = y*4 + {0..3}
    u64 a0 = 0, a1 = 0;
    #pragma unroll 4
    for (int d = 0; d < PDIM; d++) {
        u64 pv = pack2s(pet[x * PE_PAD + d]);
        u64 w0 = *(const u64*)&wt[d * PE_WPAD + y * 4];
        u64 w1 = *(const u64*)&wt[d * PE_WPAD + y * 4 + 2];
        fma2(a0, pv, w0);
        fma2(a1, pv, w1);
    }
    const int n = n0 + x;
    if (n < NPE) {
        float2 f0 = unpack2(a0), f1 = unpack2(a1);
        g_peT[(y * 4 + 0) * NPE_PAD + n] = f0.x;
        g_peT[(y * 4 + 1) * NPE_PAD + n] = f0.y;
        g_peT[(y * 4 + 2) * NPE_PAD + n] = f1.x;
        g_peT[(y * 4 + 3) * NPE_PAD + n] = f1.y;
    }
}

// ---------------- kernel 2: proj GEMM + scatter into Q/K/P ----------------
// proj[r][o] = sum_e x[r][e] * W[o][e] + bias[o],  r = seq*B + b
#define BM 64
#define BN 128
#define BK 16
__global__ void __launch_bounds__(256) proj_kernel(const float* __restrict__ x,
                                                   const float* __restrict__ w,
                                                   const float* __restrict__ bias) {
    __shared__ float As[BK][68];    // [k][m]
    __shared__ float Bs[BK][136];   // [k][n]
    const int tid = threadIdx.x;
    const int n0 = blockIdx.x * BN;
    const int m0 = blockIdx.y * BM;
    const int tx = tid & 15;        // col group: 8 cols at tx*8
    const int ty = tid >> 4;        // row group: 4 rows at ty*4

    u64 acc[4][4];
    #pragma unroll
    for (int r = 0; r < 4; r++)
        #pragma unroll
        for (int c = 0; c < 4; c++) acc[r][c] = 0ull;

    const int arow = tid >> 2;             // 0..63
    const int acol = (tid & 3) * 4;        // 0,4,8,12
    const int bn   = tid & 127;            // 0..127
    const int bk0  = (tid >> 7) * 8;       // 0 or 8
    const bool bvalid = (n0 + bn) < IN_PROJ;

    for (int k0 = 0; k0 < E_DIM; k0 += BK) {
        float4 av = *(const float4*)(x + (size_t)(m0 + arow) * E_DIM + k0 + acol);
        As[acol + 0][arow] = av.x;
        As[acol + 1][arow] = av.y;
        As[acol + 2][arow] = av.z;
        As[acol + 3][arow] = av.w;
        #pragma unroll
        for (int kb = 0; kb < 8; kb += 4) {
            float4 bv = make_float4(0.f, 0.f, 0.f, 0.f);
            if (bvalid) bv = *(const float4*)(w + (size_t)(n0 + bn) * E_DIM + k0 + bk0 + kb);
            Bs[bk0 + kb + 0][bn] = bv.x;
            Bs[bk0 + kb + 1][bn] = bv.y;
            Bs[bk0 + kb + 2][bn] = bv.z;
            Bs[bk0 + kb + 3][bn] = bv.w;
        }
        __syncthreads();
        #pragma unroll
        for (int kk = 0; kk < BK; kk++) {
            float4 a  = *(const float4*)&As[kk][ty * 4];
            float4 b0 = *(const float4*)&Bs[kk][tx * 8];
            float4 b1 = *(const float4*)&Bs[kk][tx * 8 + 4];
            u64 bb0 = pack2(b0.x, b0.y);
            u64 bb1 = pack2(b0.z, b0.w);
            u64 bb2 = pack2(b1.x, b1.y);
            u64 bb3 = pack2(b1.z, b1.w);
            u64 aa;
            aa = pack2s(a.x);
            fma2(acc[0][0], aa, bb0); fma2(acc[0][1], aa, bb1);
            fma2(acc[0][2], aa, bb2); fma2(acc[0][3], aa, bb3);
            aa = pack2s(a.y);
            fma2(acc[1][0], aa, bb0); fma2(acc[1][1], aa, bb1);
            fma2(acc[1][2], aa, bb2); fma2(acc[1][3], aa, bb3);
            aa = pack2s(a.z);
            fma2(acc[2][0], aa, bb0); fma2(acc[2][1], aa, bb1);
            fma2(acc[2][2], aa, bb2); fma2(acc[2][3], aa, bb3);
            aa = pack2s(a.w);
            fma2(acc[3][0], aa, bb0); fma2(acc[3][1], aa, bb1);
            fma2(acc[3][2], aa, bb2); fma2(acc[3][3], aa, bb3);
        }
        __syncthreads();
    }

    // epilogue: add bias, scatter to Q/K/P
    #pragma unroll
    for (int rr = 0; rr < 4; rr++) {
        int m = m0 + ty * 4 + rr;
        int seq = m >> 3;
        int b   = m & 7;
        #pragma unroll
        for (int cp = 0; cp < 4; cp++) {
            float2 f = unpack2(acc[rr][cp]);
            #pragma unroll
            for (int half = 0; half < 2; half++) {
                int o = n0 + tx * 8 + cp * 2 + half;
                if (o >= IN_PROJ) continue;
                float v = (half ? f.y : f.x) + bias[o];
                if (o < 256) {                              // q
                    int h = o >> 5, d = o & 31;
                    g_Q[(((size_t)(b * H_NUM + h)) * S_LEN + seq) * QHD + d] = v;
                } else if (o < 512) {                       // k (d-major)
                    int oo = o - 256;
                    int h = oo >> 5, d = oo & 31;
                    g_K[(((size_t)(b * H_NUM + h)) * QHD + d) * S_LEN + seq] = v;
                } else {                                    // p
                    int oo = o - 512;
                    int h = oo >> 2, d = oo & 3;
                    g_P[(((size_t)(b * H_NUM + h)) * S_LEN + seq) * PHD + d] = v;
                }
            }
        }
    }
}

// ---------------- kernel 3: fused scores + rel-shift + mask + softmax -----
// block = (qtile of 32 rows) x b x h ; 256 threads; warp w owns 4 rows,
// lane owns col pairs (jlo = t*32+lane, jhi = jlo+512), t = 0..15, packed f32x2.
#define SC_SMEM_FLOATS (QHD * S_LEN + 32 * QHD + 32 * PHD + PHD * NPE_PAD)
#define SC_SMEM_BYTES  (SC_SMEM_FLOATS * 4 + 1024)

__global__ void __launch_bounds__(256, 1)
scores_kernel(const unsigned char* __restrict__ mask, float* __restrict__ out) {
    extern __shared__ float sm[];
    float* kT = sm;                       // [32][1024]
    float* qs = kT + QHD * S_LEN;         // [32][32]
    float* ps = qs + 32 * QHD;            // [32][4]
    float* pe = ps + 32 * PHD;            // [4][2048]
    unsigned char* msk = (unsigned char*)(pe + PHD * NPE_PAD);  // [1024]

    const int i0 = blockIdx.x * 32;
    const int b  = blockIdx.y;
    const int h  = blockIdx.z;
    const int tid = threadIdx.x;
    const size_t bh = (size_t)(b * H_NUM + h);

    // --- cooperative loads (all coalesced float4) ---
    {
        const float4* kg = (const float4*)(g_K + bh * QHD * S_LEN);
        float4* kd = (float4*)kT;
        #pragma unroll 8
        for (int i = tid; i < QHD * S_LEN / 4; i += 256) kd[i] = kg[i];

        const float4* qg = (const float4*)(g_Q + (bh * S_LEN + i0) * QHD);
        ((float4*)qs)[tid] = qg[tid];

        if (tid < 32)
            ((float4*)ps)[tid] = ((const float4*)(g_P + (bh * S_LEN + i0) * PHD))[tid];

        const float4* peg = (const float4*)(g_peT + (size_t)h * PHD * NPE_PAD);
        #pragma unroll 2
        for (int i = tid; i < PHD * NPE_PAD / 4; i += 256) ((float4*)pe)[i] = peg[i];

        ((int*)msk)[tid] = ((const int*)(mask + (size_t)b * S_LEN))[tid];
    }
    __syncthreads();

    const int w = tid >> 5, lane = tid & 31;
    const int r0 = w * 4;

    u64 s2[4][16];
    #pragma unroll
    for (int rr = 0; rr < 4; rr++)
        #pragma unroll
        for (int t = 0; t < 16; t++) s2[rr][t] = 0ull;

    // --- QK^T main loop: FFMA2 over (j, j+512) column pairs ---
    #pragma unroll 2
    for (int d = 0; d < QHD; d++) {
        u64 q0 = pack2s(qs[(r0 + 0) * QHD + d]);
        u64 q1 = pack2s(qs[(r0 + 1) * QHD + d]);
        u64 q2 = pack2s(qs[(r0 + 2) * QHD + d]);
        u64 q3 = pack2s(qs[(r0 + 3) * QHD + d]);
        const float* kr = kT + d * S_LEN + lane;
        #pragma unroll
        for (int t = 0; t < 16; t++) {
            u64 kp = pack2(kr[t * 32], kr[t * 32 + 512]);
            fma2(s2[0][t], q0, kp);
            fma2(s2[1][t], q1, kp);
            fma2(s2[2][t], q2, kp);
            fma2(s2[3][t], q3, kp);
        }
    }

    // --- pos scores + mask + softmax + write, per row ---
    #pragma unroll
    for (int rr = 0; rr < 4; rr++) {
        const int i = i0 + r0 + rr;
        const u64 pp0 = pack2s(ps[(r0 + rr) * PHD + 0]);
        const u64 pp1 = pack2s(ps[(r0 + rr) * PHD + 1]);
        const u64 pp2 = pack2s(ps[(r0 + rr) * PHD + 2]);
        const u64 pp3 = pack2s(ps[(r0 + rr) * PHD + 3]);
        const int nb = (S_LEN - 1) - i + lane;     // n for jlo = t*32+lane
        float m = -1e30f;
        #pragma unroll
        for (int t = 0; t < 16; t++) {
            const int n = nb + t * 32;
            fma2(s2[rr][t], pp0, pack2(pe[n],            pe[n + 512]));
            fma2(s2[rr][t], pp1, pack2(pe[NPE_PAD + n],  pe[NPE_PAD + n + 512]));
            fma2(s2[rr][t], pp2, pack2(pe[2*NPE_PAD + n],pe[2*NPE_PAD + n + 512]));
            fma2(s2[rr][t], pp3, pack2(pe[3*NPE_PAD + n],pe[3*NPE_PAD + n + 512]));
            float2 f = unpack2(s2[rr][t]);
            const int jlo = t * 32 + lane;
            if (msk[jlo])       f.x = -1000.0f;
            if (msk[jlo + 512]) f.y = -1000.0f;
            s2[rr][t] = pack2(f.x, f.y);
            m = fmaxf(m, fmaxf(f.x, f.y));
        }
        #pragma unroll
        for (int off = 16; off > 0; off >>= 1)
            m = fmaxf(m, __shfl_xor_sync(0xffffffffu, m, off));
        float sum = 0.f;
        #pragma unroll
        for (int t = 0; t < 16; t++) {
            float2 f = unpack2(s2[rr][t]);
            f.x = __expf(f.x - m);
            f.y = __expf(f.y - m);
            sum += f.x + f.y;
            s2[rr][t] = pack2(f.x, f.y);
        }
        #pragma unroll
        for (int off = 16; off > 0; off >>= 1)
            sum += __shfl_xor_sync(0xffffffffu, sum, off);
        const float inv = 1.0f / sum;
        float* orow = out + ((((size_t)h * B_SZ + b) * S_LEN + i) << 10);
        #pragma unroll
        for (int t = 0; t < 16; t++) {
            float2 f = unpack2(s2[rr][t]);
            orow[t * 32 + lane]       = f.x * inv;
            orow[t * 32 + 512 + lane] = f.y * inv;
        }
    }
}

// ---------------- launch ----------------
extern "C" void kernel_launch(void* const* d_in, const int* in_sizes, int n_in,
                              void* d_out, int out_size) {
    const float* x        = (const float*)d_in[0];
    const float* pos_emb  = (const float*)d_in[1];
    const unsigned char* kpm = (const unsigned char*)d_in[2];
    const float* in_w     = (const float*)d_in[3];
    const float* in_b     = (const float*)d_in[4];
    const float* lpw      = (const float*)d_in[5];
    float* out = (float*)d_out;

    // pe
    {
        cudaFuncSetAttribute(pe_kernel,
                             cudaFuncAttributeMaxDynamicSharedMemorySize,
                             PE_SMEM_BYTES);
        dim3 blk(32, 8);
        dim3 grd((NPE + PE_NB - 1) / PE_NB);
        pe_kernel<<<grd, blk, PE_SMEM_BYTES>>>(pos_emb, lpw);
    }
    // proj GEMM: M=8192, N=544, K=512
    {
        dim3 grd((IN_PROJ + BN - 1) / BN, (S_LEN * B_SZ) / BM);
        proj_kernel<<<grd, 256>>>(x, in_w, in_b);
    }
    // fused scores + softmax
    {
        cudaFuncSetAttribute(scores_kernel,
                             cudaFuncAttributeMaxDynamicSharedMemorySize,
                             SC_SMEM_BYTES);
        dim3 grd(S_LEN / 32, B_SZ, H_NUM);
        scores_kernel<<<grd, 256, SC_SMEM_BYTES>>>(kpm, out);
    }
}

// round 6
// speedup vs baseline: 1.1271x; 1.1271x over previous
#include <cuda_runtime.h>
#include <cuda_bf16.h>
#include <cstdint>

#define S_LEN 1024
#define B_SZ  8
#define E_DIM 512
#define H_NUM 8
#define QHD   32
#define PHD   4
#define PDIM  192
#define IN_PROJ 544
#define NPE   2047

typedef unsigned int u32;

// ---------------- device scratch ----------------
__device__ __nv_bfloat16 g_Qs[B_SZ * H_NUM * S_LEN * 64];  // [bh][s][Qh(32)|Ql(32)]
__device__ __nv_bfloat16 g_Ks[B_SZ * H_NUM * S_LEN * 64];  // [bh][s][Kh(32)|Kl(32)]
__device__ float g_P[B_SZ * H_NUM * S_LEN * PHD];          // [bh][s][p]
__device__ float g_pe4[H_NUM * 2048 * 4];                  // [h][n][p]

__device__ __forceinline__ u32 s2u(const void* p) {
    u32 a; asm("{ .reg .u64 t; cvta.to.shared.u64 t, %1; cvt.u32.u64 %0, t; }"
               : "=r"(a) : "l"(p)); return a;
}

// ---------------- kernel 1: pe4[h][n][p] = pos_emb[n] . lpw[h*4+p] --------
__global__ void pe_kernel(const float* __restrict__ pos_emb,
                          const float* __restrict__ lpw) {
    int hp = threadIdx.x;                       // 0..31
    int n  = blockIdx.x * blockDim.y + threadIdx.y;
    if (n >= NPE) return;
    const float4* pe4 = (const float4*)(pos_emb + (size_t)n * PDIM);
    const float4* w4  = (const float4*)(lpw + (size_t)hp * PDIM);
    float acc = 0.f;
    #pragma unroll 8
    for (int d = 0; d < PDIM / 4; d++) {
        float4 a = pe4[d];
        float4 b = w4[d];
        acc += a.x * b.x + a.y * b.y + a.z * b.z + a.w * b.w;
    }
    g_pe4[(((hp >> 2) * 2048) + n) * 4 + (hp & 3)] = acc;
}

// ---------------- kernel 2: proj GEMM + split-bf16 scatter ----------------
#define BM 64
#define BN 64
#define BK 16
__global__ void __launch_bounds__(256) proj_kernel(const float* __restrict__ x,
                                                   const float* __restrict__ w,
                                                   const float* __restrict__ bias) {
    __shared__ float As[BK][68];
    __shared__ float Bs[BK][68];
    const int tid = threadIdx.x;
    const int n0 = blockIdx.x * BN;
    const int m0 = blockIdx.y * BM;
    const int tx = tid & 15, ty = tid >> 4;

    float acc[4][4] = {};

    const int arow = tid >> 2;
    const int acol = (tid & 3) * 4;
    const int bn   = tid & 63;
    const int bk   = (tid >> 6) * 4;
    const bool bvalid = (n0 + bn) < IN_PROJ;

    for (int k0 = 0; k0 < E_DIM; k0 += BK) {
        float4 av = *(const float4*)(x + (size_t)(m0 + arow) * E_DIM + k0 + acol);
        As[acol + 0][arow] = av.x;
        As[acol + 1][arow] = av.y;
        As[acol + 2][arow] = av.z;
        As[acol + 3][arow] = av.w;
        float4 bv = make_float4(0.f, 0.f, 0.f, 0.f);
        if (bvalid) bv = *(const float4*)(w + (size_t)(n0 + bn) * E_DIM + k0 + bk);
        Bs[bk + 0][bn] = bv.x;
        Bs[bk + 1][bn] = bv.y;
        Bs[bk + 2][bn] = bv.z;
        Bs[bk + 3][bn] = bv.w;
        __syncthreads();
        #pragma unroll
        for (int kk = 0; kk < BK; kk++) {
            float a[4], bb[4];
            *(float4*)a  = *(const float4*)&As[kk][ty * 4];
            *(float4*)bb = *(const float4*)&Bs[kk][tx * 4];
            #pragma unroll
            for (int rr = 0; rr < 4; rr++)
                #pragma unroll
                for (int cc = 0; cc < 4; cc++)
                    acc[rr][cc] = fmaf(a[rr], bb[cc], acc[rr][cc]);
        }
        __syncthreads();
    }

    #pragma unroll
    for (int rr = 0; rr < 4; rr++) {
        int m = m0 + ty * 4 + rr;
        int seq = m >> 3;
        int b   = m & 7;
        #pragma unroll
        for (int cc = 0; cc < 4; cc++) {
            int o = n0 + tx * 4 + cc;
            if (o >= IN_PROJ) continue;
            float v = acc[rr][cc] + bias[o];
            if (o < 512) {                                // q or k -> split bf16
                int oo = o & 255;
                int h = oo >> 5, d = oo & 31;
                __nv_bfloat16 hi = __float2bfloat16(v);
                __nv_bfloat16 lo = __float2bfloat16(v - __bfloat162float(hi));
                __nv_bfloat16* dst = (o < 256 ? g_Qs : g_Ks) +
                                     ((size_t)(b * H_NUM + h) * S_LEN + seq) * 64;
                dst[d]      = hi;
                dst[32 + d] = lo;
            } else {
                int oo = o - 512;
                int h = oo >> 2, d = oo & 3;
                g_P[((size_t)(b * H_NUM + h) * S_LEN + seq) * PHD + d] = v;
            }
        }
    }
}

// ---------------- kernel 3: HMMA scores + pos + softmax -------------------
// block = 32 q-rows x (b,h); 8 warps; warp w owns cols [w*128, w*128+128).
// mma.sync m16n8k16 bf16 with hi/lo split (3 products, 6 k16-steps).
#define OFF_K   0                 // 1024 x 128B, XOR-swizzled
#define OFF_Q   131072            // 32 x 128B, XOR-swizzled
#define OFF_PE  135168            // [1056][4] f32 window
#define OFF_MSK 152064            // [1024] u8
#define OFF_PS  153088            // [32][4] f32
#define OFF_SUM 153600            // [32] f32
#define OFF_STG 153728            // 8 x [16][132] f32 = 67584
#define SC_SMEM 221312

#define SWZ(r, c16) ((((c16) ^ ((r) & 7)) << 4))

#define LDSM_X4(a0,a1,a2,a3, addr) \
    asm volatile("ldmatrix.sync.aligned.m8n8.x4.shared.b16 {%0,%1,%2,%3}, [%4];" \
        : "=r"(a0), "=r"(a1), "=r"(a2), "=r"(a3) : "r"(addr))
#define LDSM_X2(b0,b1, addr) \
    asm volatile("ldmatrix.sync.aligned.m8n8.x2.shared.b16 {%0,%1}, [%2];" \
        : "=r"(b0), "=r"(b1) : "r"(addr))
#define MMA16816(c, a, b0, b1) \
    asm volatile("mma.sync.aligned.m16n8k16.row.col.f32.bf16.bf16.f32 " \
        "{%0,%1,%2,%3}, {%4,%5,%6,%7}, {%8,%9}, {%0,%1,%2,%3};" \
        : "+f"((c)[0]), "+f"((c)[1]), "+f"((c)[2]), "+f"((c)[3]) \
        : "r"((a)[0]), "r"((a)[1]), "r"((a)[2]), "r"((a)[3]), "r"(b0), "r"(b1))

__global__ void __launch_bounds__(256, 1)
scores_kernel(const unsigned char* __restrict__ mask, float* __restrict__ out) {
    extern __shared__ __align__(128) char smem[];
    const u32 sbase = s2u(smem);

    const int i0 = blockIdx.x * 32;
    const int b  = blockIdx.y;
    const int h  = blockIdx.z;
    const int tid = threadIdx.x;
    const size_t bh = (size_t)(b * H_NUM + h);

    // ---- cooperative loads ----
    {
        const float4* ks = (const float4*)(g_Ks + bh * (size_t)S_LEN * 64);
        #pragma unroll 8
        for (int t = tid; t < 8192; t += 256) {
            int row = t >> 3, c16 = t & 7;
            *(float4*)(smem + OFF_K + row * 128 + SWZ(row, c16)) = ks[t];
        }
        const float4* qs = (const float4*)(g_Qs + (bh * S_LEN + i0) * 64);
        {
            int row = tid >> 3, c16 = tid & 7;
            *(float4*)(smem + OFF_Q + row * 128 + SWZ(row, c16)) = qs[tid];
        }
        const int nlo = 992 - i0;
        const float4* peg = (const float4*)(g_pe4 + (size_t)h * 2048 * 4);
        #pragma unroll 2
        for (int t = tid; t < 1056; t += 256)
            ((float4*)(smem + OFF_PE))[t] = peg[nlo + t];
        ((int*)(smem + OFF_MSK))[tid] = ((const int*)(mask + (size_t)b * S_LEN))[tid];
        if (tid < 32) {
            ((float4*)(smem + OFF_PS))[tid] = ((const float4*)(g_P + (bh * S_LEN + i0) * PHD))[tid];
            ((float*)(smem + OFF_SUM))[tid] = 0.f;
        }
    }
    __syncthreads();

    const int w = tid >> 5, lane = tid & 31;
    const int jb = w * 128;
    const int g = lane >> 2, t2 = (lane & 3) * 2;

    float acc[2][16][4];
    #pragma unroll
    for (int mt = 0; mt < 2; mt++)
        #pragma unroll
        for (int nt = 0; nt < 16; nt++)
            #pragma unroll
            for (int e = 0; e < 4; e++) acc[mt][nt][e] = 0.f;

    // A/B c16 offsets per k-step: (Qh,Kh)x2, (Ql,Kh)x2, (Qh,Kl)x2
    const int ac16[6] = {0, 2, 4, 6, 0, 2};
    const int bc16[6] = {0, 2, 0, 2, 4, 6};

    const int a_row = lane & 15;
    const int a_hi  = (lane >> 4) & 1;
    const int b_row = jb + (lane & 7);
    const int b_hi  = (lane >> 3) & 1;

    #pragma unroll
    for (int s = 0; s < 6; s++) {
        u32 afrag[2][4];
        #pragma unroll
        for (int mt = 0; mt < 2; mt++) {
            int r = mt * 16 + a_row;
            u32 ad = sbase + OFF_Q + r * 128 + SWZ(r, ac16[s] + a_hi);
            LDSM_X4(afrag[mt][0], afrag[mt][1], afrag[mt][2], afrag[mt][3], ad);
        }
        #pragma unroll
        for (int nt = 0; nt < 16; nt++) {
            int r = b_row + nt * 8;
            u32 bd = sbase + OFF_K + r * 128 + SWZ(r, bc16[s] + b_hi);
            u32 b0, b1;
            LDSM_X2(b0, b1, bd);
            MMA16816(acc[0][nt], afrag[0], b0, b1);
            MMA16816(acc[1][nt], afrag[1], b0, b1);
        }
    }

    // ---- pass 1: pos + mask + exp (in place) + row sums ----
    const float* pef = (const float*)(smem + OFF_PE);
    const float* psf = (const float*)(smem + OFF_PS);
    const unsigned char* msk = (const unsigned char*)(smem + OFF_MSK);
    float* sums = (float*)(smem + OFF_SUM);

    #pragma unroll
    for (int mt = 0; mt < 2; mt++) {
        const int r1 = mt * 16 + g;          // local rows r1, r1+8
        const float4 pw1 = *(const float4*)(psf + r1 * 4);
        const float4 pw2 = *(const float4*)(psf + (r1 + 8) * 4);
        float ps1 = 0.f, ps2 = 0.f;
        #pragma unroll
        for (int nt = 0; nt < 16; nt++) {
            const int j = jb + nt * 8 + t2;
            const int nr = 31 - r1 + j;      // pe window index for (r1, j)
            float4 p0 = *(const float4*)(pef + (size_t)nr * 4);
            float4 p1 = *(const float4*)(pef + (size_t)(nr + 1) * 4);
            float4 p2 = *(const float4*)(pef + (size_t)(nr - 8) * 4);
            float4 p3 = *(const float4*)(pef + (size_t)(nr - 7) * 4);
            const bool m0 = msk[j], m1 = msk[j + 1];
            float s0 = acc[mt][nt][0] + pw1.x*p0.x + pw1.y*p0.y + pw1.z*p0.z + pw1.w*p0.w;
            float s1 = acc[mt][nt][1] + pw1.x*p1.x + pw1.y*p1.y + pw1.z*p1.z + pw1.w*p1.w;
            float s2 = acc[mt][nt][2] + pw2.x*p2.x + pw2.y*p2.y + pw2.z*p2.z + pw2.w*p2.w;
            float s3 = acc[mt][nt][3] + pw2.x*p3.x + pw2.y*p3.y + pw2.z*p3.z + pw2.w*p3.w;
            if (m0) { s0 = -1000.f; s2 = -1000.f; }
            if (m1) { s1 = -1000.f; s3 = -1000.f; }
            float e0 = __expf(s0), e1 = __expf(s1), e2 = __expf(s2), e3 = __expf(s3);
            acc[mt][nt][0] = e0; acc[mt][nt][1] = e1;
            acc[mt][nt][2] = e2; acc[mt][nt][3] = e3;
            ps1 += e0 + e1; ps2 += e2 + e3;
        }
        ps1 += __shfl_xor_sync(0xffffffffu, ps1, 1);
        ps1 += __shfl_xor_sync(0xffffffffu, ps1, 2);
        ps2 += __shfl_xor_sync(0xffffffffu, ps2, 1);
        ps2 += __shfl_xor_sync(0xffffffffu, ps2, 2);
        if ((lane & 3) == 0) {
            atomicAdd(&sums[r1], ps1);
            atomicAdd(&sums[r1 + 8], ps2);
        }
    }
    __syncthreads();
    if (tid < 32) sums[tid] = 1.0f / sums[tid];
    __syncthreads();

    // ---- pass 2: scale + coalesced write via smem transpose ----
    float* stg = (float*)(smem + OFF_STG) + w * 2112;   // [16][132]
    #pragma unroll
    for (int mt = 0; mt < 2; mt++) {
        const int r1 = mt * 16 + g;
        const float inv1 = sums[r1];
        const float inv2 = sums[r1 + 8];
        #pragma unroll
        for (int nt = 0; nt < 16; nt++) {
            const int c = nt * 8 + t2;
            *(float2*)(stg + g * 132 + c)       = make_float2(acc[mt][nt][0] * inv1, acc[mt][nt][1] * inv1);
            *(float2*)(stg + (g + 8) * 132 + c) = make_float2(acc[mt][nt][2] * inv2, acc[mt][nt][3] * inv2);
        }
        __syncwarp();
        float* ob = out + (((size_t)(h * B_SZ + b) * S_LEN + i0 + mt * 16) << 10) + jb;
        #pragma unroll
        for (int it = 0; it < 16; it++) {
            float4 v = *(const float4*)(stg + it * 132 + lane * 4);
            *(float4*)(ob + ((size_t)it << 10) + lane * 4) = v;
        }
        __syncwarp();
    }
}

// ---------------- launch ----------------
extern "C" void kernel_launch(void* const* d_in, const int* in_sizes, int n_in,
                              void* d_out, int out_size) {
    const float* x        = (const float*)d_in[0];
    const float* pos_emb  = (const float*)d_in[1];
    const unsigned char* kpm = (const unsigned char*)d_in[2];
    const float* in_w     = (const float*)d_in[3];
    const float* in_b     = (const float*)d_in[4];
    const float* lpw      = (const float*)d_in[5];
    float* out = (float*)d_out;

    {
        dim3 blk(32, 8);
        dim3 grd((NPE + 7) / 8);
        pe_kernel<<<grd, blk>>>(pos_emb, lpw);
    }
    {
        dim3 grd((IN_PROJ + BN - 1) / BN, (S_LEN * B_SZ) / BM);
        proj_kernel<<<grd, 256>>>(x, in_w, in_b);
    }
    {
        cudaFuncSetAttribute(scores_kernel,
                             cudaFuncAttributeMaxDynamicSharedMemorySize, SC_SMEM);
        dim3 grd(S_LEN / 32, B_SZ, H_NUM);
        scores_kernel<<<grd, 256, SC_SMEM>>>(kpm, out);
    }
}

// round 11
// speedup vs baseline: 1.2683x; 1.1253x over previous
#include <cuda_runtime.h>
#include <cuda_bf16.h>
#include <cstdint>

#define S_LEN 1024
#define B_SZ  8
#define E_DIM 512
#define H_NUM 8
#define QHD   32
#define PHD   4
#define PDIM  192
#define IN_PROJ 544
#define NPE   2047

typedef unsigned int u32;

// ---------------- device scratch ----------------
__device__ __nv_bfloat16 g_Qs[B_SZ * H_NUM * S_LEN * 64];  // [bh][s][Qh|Ql]
__device__ __nv_bfloat16 g_Ks[B_SZ * H_NUM * S_LEN * 64];  // [bh][s][Kh|Kl]
__device__ float g_P[B_SZ * H_NUM * S_LEN * PHD];          // [bh][s][p]
__device__ float g_pe4[H_NUM * 2048 * 4];                  // [h][n][p]
__device__ __nv_bfloat16 g_Xh[8192 * E_DIM];               // x hi split
__device__ __nv_bfloat16 g_Xl[8192 * E_DIM];               // x lo split
__device__ __nv_bfloat16 g_Wh[IN_PROJ * E_DIM];
__device__ __nv_bfloat16 g_Wl[IN_PROJ * E_DIM];

__device__ __forceinline__ u32 s2u(const void* p) {
    u32 a; asm("{ .reg .u64 t; cvta.to.shared.u64 t, %1; cvt.u32.u64 %0, t; }"
               : "=r"(a) : "l"(p)); return a;
}

#define SWZ(r, c16) ((((c16) ^ ((r) & 7)) << 4))

#define LDSM_X4(a0,a1,a2,a3, addr) \
    asm volatile("ldmatrix.sync.aligned.m8n8.x4.shared.b16 {%0,%1,%2,%3}, [%4];" \
        : "=r"(a0), "=r"(a1), "=r"(a2), "=r"(a3) : "r"(addr))
#define LDSM_X2(b0,b1, addr) \
    asm volatile("ldmatrix.sync.aligned.m8n8.x2.shared.b16 {%0,%1}, [%2];" \
        : "=r"(b0), "=r"(b1) : "r"(addr))
#define MMA16816(c, a, b0, b1) \
    asm volatile("mma.sync.aligned.m16n8k16.row.col.f32.bf16.bf16.f32 " \
        "{%0,%1,%2,%3}, {%4,%5,%6,%7}, {%8,%9}, {%0,%1,%2,%3};" \
        : "+f"((c)[0]), "+f"((c)[1]), "+f"((c)[2]), "+f"((c)[3]) \
        : "r"((a)[0]), "r"((a)[1]), "r"((a)[2]), "r"((a)[3]), "r"(b0), "r"(b1))

// ---------------- split prepass kernels ----------------
__global__ void xsplit_kernel(const float* __restrict__ x) {
    size_t i = ((size_t)blockIdx.x * 256 + threadIdx.x) * 4;
    float4 v = *(const float4*)(x + i);
    __nv_bfloat16 h0 = __float2bfloat16(v.x);
    __nv_bfloat16 h1 = __float2bfloat16(v.y);
    __nv_bfloat16 h2 = __float2bfloat16(v.z);
    __nv_bfloat16 h3 = __float2bfloat16(v.w);
    __nv_bfloat162 a, b;
    a.x = h0; a.y = h1; b.x = h2; b.y = h3;
    ((__nv_bfloat162*)(g_Xh + i))[0] = a;
    ((__nv_bfloat162*)(g_Xh + i))[1] = b;
    a.x = __float2bfloat16(v.x - __bfloat162float(h0));
    a.y = __float2bfloat16(v.y - __bfloat162float(h1));
    b.x = __float2bfloat16(v.z - __bfloat162float(h2));
    b.y = __float2bfloat16(v.w - __bfloat162float(h3));
    ((__nv_bfloat162*)(g_Xl + i))[0] = a;
    ((__nv_bfloat162*)(g_Xl + i))[1] = b;
}

__global__ void wsplit_kernel(const float* __restrict__ w) {
    size_t i = ((size_t)blockIdx.x * 256 + threadIdx.x) * 4;
    float4 v = *(const float4*)(w + i);
    __nv_bfloat16 h0 = __float2bfloat16(v.x);
    __nv_bfloat16 h1 = __float2bfloat16(v.y);
    __nv_bfloat16 h2 = __float2bfloat16(v.z);
    __nv_bfloat16 h3 = __float2bfloat16(v.w);
    __nv_bfloat162 a, b;
    a.x = h0; a.y = h1; b.x = h2; b.y = h3;
    ((__nv_bfloat162*)(g_Wh + i))[0] = a;
    ((__nv_bfloat162*)(g_Wh + i))[1] = b;
    a.x = __float2bfloat16(v.x - __bfloat162float(h0));
    a.y = __float2bfloat16(v.y - __bfloat162float(h1));
    b.x = __float2bfloat16(v.z - __bfloat162float(h2));
    b.y = __float2bfloat16(v.w - __bfloat162float(h3));
    ((__nv_bfloat162*)(g_Wl + i))[0] = a;
    ((__nv_bfloat162*)(g_Wl + i))[1] = b;
}

// ---------------- pe kernel (smem-tiled) ----------------
#define PE_NB 32
#define PE_PAD 193
#define PE_WPAD 34
#define PE_SMEM_BYTES ((PE_NB * PE_PAD + PDIM * PE_WPAD) * 4)
__global__ void __launch_bounds__(256) pe_kernel(const float* __restrict__ pos_emb,
                                                 const float* __restrict__ lpw) {
    extern __shared__ __align__(128) char smem_dyn[];
    float* pesm = (float*)smem_dyn;
    float* pet = pesm;                          // [32][193]
    float* wt  = pesm + PE_NB * PE_PAD;         // [192][34]
    const int tid = threadIdx.y * 32 + threadIdx.x;
    const int n0 = blockIdx.x * PE_NB;

    for (int idx = tid; idx < PE_NB * (PDIM / 4); idx += 256) {
        int r = idx / (PDIM / 4), c = (idx % (PDIM / 4)) * 4;
        float4 v = make_float4(0.f, 0.f, 0.f, 0.f);
        if (n0 + r < NPE) v = *(const float4*)(pos_emb + (size_t)(n0 + r) * PDIM + c);
        pet[r * PE_PAD + c + 0] = v.x;
        pet[r * PE_PAD + c + 1] = v.y;
        pet[r * PE_PAD + c + 2] = v.z;
        pet[r * PE_PAD + c + 3] = v.w;
    }
    for (int idx = tid; idx < 32 * (PDIM / 4); idx += 256) {
        int r = idx / (PDIM / 4), c = (idx % (PDIM / 4)) * 4;
        float4 v = *(const float4*)(lpw + (size_t)r * PDIM + c);
        wt[(c + 0) * PE_WPAD + r] = v.x;
        wt[(c + 1) * PE_WPAD + r] = v.y;
        wt[(c + 2) * PE_WPAD + r] = v.z;
        wt[(c + 3) * PE_WPAD + r] = v.w;
    }
    __syncthreads();

    const int x = threadIdx.x;     // n_local
    const int y = threadIdx.y;     // h
    float a0 = 0.f, a1 = 0.f, a2 = 0.f, a3 = 0.f;
    #pragma unroll 4
    for (int d = 0; d < PDIM; d++) {
        float pv = pet[x * PE_PAD + d];
        const float* wr = wt + d * PE_WPAD + y * 4;
        a0 = fmaf(pv, wr[0], a0);
        a1 = fmaf(pv, wr[1], a1);
        a2 = fmaf(pv, wr[2], a2);
        a3 = fmaf(pv, wr[3], a3);
    }
    const int n = n0 + x;
    if (n < NPE)
        ((float4*)g_pe4)[y * 2048 + n] = make_float4(a0, a1, a2, a3);
}

// ---------------- proj: HMMA bf16-split GEMM + scatter --------------------
// C[8192][544] = X[8192][512] @ W^T.  block 128x64, 8 warps (4x2).
#define PJ_XH 0
#define PJ_XL 16384
#define PJ_WH 32768
#define PJ_WL 40960
#define PJ_SMEM 49152

__device__ __forceinline__ void proj_scatter(int m, int o, float v,
                                             const float* __restrict__ bias) {
    v += bias[o];
    int seq = m >> 3, b = m & 7;
    if (o < 512) {
        int oo = o & 255;
        int h = oo >> 5, d = oo & 31;
        __nv_bfloat16 hi = __float2bfloat16(v);
        __nv_bfloat16 lo = __float2bfloat16(v - __bfloat162float(hi));
        __nv_bfloat16* dst = (o < 256 ? g_Qs : g_Ks) +
                             ((size_t)(b * H_NUM + h) * S_LEN + seq) * 64;
        dst[d] = hi;
        dst[32 + d] = lo;
    } else {
        int oo = o - 512;
        g_P[((size_t)(b * H_NUM + (oo >> 2)) * S_LEN + seq) * PHD + (oo & 3)] = v;
    }
}

__global__ void __launch_bounds__(256) proj_mma_kernel(const float* __restrict__ bias) {
    extern __shared__ __align__(128) char smem_dyn[];
    char* psm = smem_dyn;
    const u32 pb = s2u(psm);
    const int tid = threadIdx.x;
    const int w = tid >> 5, lane = tid & 31;
    const int wm = w & 3, wn = w >> 2;
    const int m0 = blockIdx.y * 128;
    const int n0 = blockIdx.x * 64;

    float acc[2][4][4];
    #pragma unroll
    for (int mt = 0; mt < 2; mt++)
        #pragma unroll
        for (int nt = 0; nt < 4; nt++)
            #pragma unroll
            for (int e = 0; e < 4; e++) acc[mt][nt][e] = 0.f;

    const int a_row = lane & 15, a_hi = (lane >> 4) & 1;
    const int b_lane = lane & 7, b_hi = (lane >> 3) & 1;

    for (int k0 = 0; k0 < E_DIM; k0 += 64) {
        for (int t = tid; t < 1024; t += 256) {
            int row = t >> 3, c16 = t & 7;
            size_t src = (size_t)(m0 + row) * E_DIM + k0 + c16 * 8;
            *(float4*)(psm + PJ_XH + row * 128 + SWZ(row, c16)) = *(const float4*)(g_Xh + src);
            *(float4*)(psm + PJ_XL + row * 128 + SWZ(row, c16)) = *(const float4*)(g_Xl + src);
        }
        for (int t = tid; t < 512; t += 256) {
            int row = t >> 3, c16 = t & 7;
            int n = n0 + row;
            float4 vh = make_float4(0.f, 0.f, 0.f, 0.f), vl = vh;
            if (n < IN_PROJ) {
                size_t src = (size_t)n * E_DIM + k0 + c16 * 8;
                vh = *(const float4*)(g_Wh + src);
                vl = *(const float4*)(g_Wl + src);
            }
            *(float4*)(psm + PJ_WH + row * 128 + SWZ(row, c16)) = vh;
            *(float4*)(psm + PJ_WL + row * 128 + SWZ(row, c16)) = vl;
        }
        __syncthreads();

        #pragma unroll
        for (int ks = 0; ks < 4; ks++) {
            u32 ah[2][4], al[2][4];
            #pragma unroll
            for (int mt = 0; mt < 2; mt++) {
                int r = wm * 32 + mt * 16 + a_row;
                LDSM_X4(ah[mt][0], ah[mt][1], ah[mt][2], ah[mt][3],
                        pb + PJ_XH + r * 128 + SWZ(r, ks * 2 + a_hi));
                LDSM_X4(al[mt][0], al[mt][1], al[mt][2], al[mt][3],
                        pb + PJ_XL + r * 128 + SWZ(r, ks * 2 + a_hi));
            }
            #pragma unroll
            for (int nt = 0; nt < 4; nt++) {
                int r = wn * 32 + nt * 8 + b_lane;
                u32 bh0, bh1, bl0, bl1;
                LDSM_X2(bh0, bh1, pb + PJ_WH + r * 128 + SWZ(r, ks * 2 + b_hi));
                LDSM_X2(bl0, bl1, pb + PJ_WL + r * 128 + SWZ(r, ks * 2 + b_hi));
                #pragma unroll
                for (int mt = 0; mt < 2; mt++) {
                    MMA16816(acc[mt][nt], ah[mt], bh0, bh1);
                    MMA16816(acc[mt][nt], al[mt], bh0, bh1);
                    MMA16816(acc[mt][nt], ah[mt], bl0, bl1);
                }
            }
        }
        __syncthreads();
    }

    const int g = lane >> 2, t2 = (lane & 3) * 2;
    #pragma unroll
    for (int mt = 0; mt < 2; mt++) {
        #pragma unroll
        for (int nt = 0; nt < 4; nt++) {
            int o0 = n0 + wn * 32 + nt * 8 + t2;
            int m1 = m0 + wm * 32 + mt * 16 + g;
            if (o0 < IN_PROJ) {
                proj_scatter(m1,     o0, acc[mt][nt][0], bias);
                proj_scatter(m1 + 8, o0, acc[mt][nt][2], bias);
            }
            if (o0 + 1 < IN_PROJ) {
                proj_scatter(m1,     o0 + 1, acc[mt][nt][1], bias);
                proj_scatter(m1 + 8, o0 + 1, acc[mt][nt][3], bias);
            }
        }
    }
}

// ---------------- scores: HMMA + diag pos pass + softmax ------------------
#define SSTRIDE 1028                  // floats; pad for conflict-free frag dump
#define OFF_S   0                     // K tile (load/mma) then S_c [32][1028]
#define OFF_Q   131584
#define OFF_PE  135680                // [1056] float4
#define OFF_MSK 152576                // [1024] u8
#define OFF_PS  153600                // [32][4] f32
#define OFF_SUM 154112                // [32] f32
#define SC_SMEM 154368

__global__ void __launch_bounds__(256, 1)
scores_kernel(const unsigned char* __restrict__ mask, float* __restrict__ out) {
    extern __shared__ __align__(128) char smem_dyn[];
    char* smem = smem_dyn;
    const u32 sbase = s2u(smem);

    const int i0 = blockIdx.x * 32;
    const int b  = blockIdx.y;
    const int h  = blockIdx.z;
    const int tid = threadIdx.x;
    const size_t bh = (size_t)(b * H_NUM + h);

    // ---- cooperative loads ----
    {
        const float4* ks = (const float4*)(g_Ks + bh * (size_t)S_LEN * 64);
        #pragma unroll 8
        for (int t = tid; t < 8192; t += 256) {
            int row = t >> 3, c16 = t & 7;
            *(float4*)(smem + OFF_S + row * 128 + SWZ(row, c16)) = ks[t];
        }
        const float4* qs = (const float4*)(g_Qs + (bh * S_LEN + i0) * 64);
        {
            int row = tid >> 3, c16 = tid & 7;
            *(float4*)(smem + OFF_Q + row * 128 + SWZ(row, c16)) = qs[tid];
        }
        const int nlo = 992 - i0;
        const float4* peg = (const float4*)(g_pe4 + (size_t)h * 2048 * 4);
        #pragma unroll 2
        for (int t = tid; t < 1056; t += 256)
            ((float4*)(smem + OFF_PE))[t] = peg[nlo + t];
        ((int*)(smem + OFF_MSK))[tid] = ((const int*)(mask + (size_t)b * S_LEN))[tid];
        if (tid < 32)
            ((float4*)(smem + OFF_PS))[tid] = ((const float4*)(g_P + (bh * S_LEN + i0) * PHD))[tid];
    }
    __syncthreads();

    const int w = tid >> 5, lane = tid & 31;
    const int jb = w * 128;
    const int g = lane >> 2, t2 = (lane & 3) * 2;

    float acc[2][16][4];
    #pragma unroll
    for (int mt = 0; mt < 2; mt++)
        #pragma unroll
        for (int nt = 0; nt < 16; nt++)
            #pragma unroll
            for (int e = 0; e < 4; e++) acc[mt][nt][e] = 0.f;

    const int ac16[6] = {0, 2, 4, 6, 0, 2};
    const int bc16[6] = {0, 2, 0, 2, 4, 6};
    const int a_row = lane & 15;
    const int a_hi  = (lane >> 4) & 1;
    const int b_row = jb + (lane & 7);
    const int b_hi  = (lane >> 3) & 1;

    #pragma unroll
    for (int s = 0; s < 6; s++) {
        u32 afrag[2][4];
        #pragma unroll
        for (int mt = 0; mt < 2; mt++) {
            int r = mt * 16 + a_row;
            u32 ad = sbase + OFF_Q + r * 128 + SWZ(r, ac16[s] + a_hi);
            LDSM_X4(afrag[mt][0], afrag[mt][1], afrag[mt][2], afrag[mt][3], ad);
        }
        #pragma unroll
        for (int nt = 0; nt < 16; nt++) {
            int r = b_row + nt * 8;
            u32 bd = sbase + OFF_S + r * 128 + SWZ(r, bc16[s] + b_hi);
            u32 b0, b1;
            LDSM_X2(b0, b1, bd);
            MMA16816(acc[0][nt], afrag[0], b0, b1);
            MMA16816(acc[1][nt], afrag[1], b0, b1);
        }
    }
    __syncthreads();   // all warps done reading K before S_c overwrite

    // ---- dump content scores to smem (stride-padded) ----
    float* S = (float*)(smem + OFF_S);
    #pragma unroll
    for (int mt = 0; mt < 2; mt++) {
        const int r1 = mt * 16 + g;
        #pragma unroll
        for (int nt = 0; nt < 16; nt++) {
            const int c = jb + nt * 8 + t2;
            *(float2*)(S + r1 * SSTRIDE + c)       = make_float2(acc[mt][nt][0], acc[mt][nt][1]);
            *(float2*)(S + (r1 + 8) * SSTRIDE + c) = make_float2(acc[mt][nt][2], acc[mt][nt][3]);
        }
    }
    __syncthreads();

    // ---- diagonal pass: pos + mask + exp, pe loaded once per lane --------
    const float4* pef4 = (const float4*)(smem + OFF_PE);
    const float*  psf  = (const float*)(smem + OFF_PS);
    const unsigned char* msk = (const unsigned char*)(smem + OFF_MSK);
    for (int c = w; c < 33; c += 8) {
        const int nw = c * 32 + lane;        // 0..1055
        const float4 pv = pef4[nw];
        #pragma unroll 4
        for (int r = 0; r < 32; r++) {
            const int j = nw - 31 + r;
            if (j >= 0 && j < 1024) {
                const float4 pw = *(const float4*)(psf + r * 4);   // broadcast
                float v = S[r * SSTRIDE + j];
                v = fmaf(pw.x, pv.x, v); v = fmaf(pw.y, pv.y, v);
                v = fmaf(pw.z, pv.z, v); v = fmaf(pw.w, pv.w, v);
                if (msk[j]) v = -1000.f;
                S[r * SSTRIDE + j] = __expf(v);
            }
        }
    }
    __syncthreads();

    // ---- row sums (warp w owns rows 4w..4w+3) ----
    float* sums = (float*)(smem + OFF_SUM);
    #pragma unroll
    for (int rr = 0; rr < 4; rr++) {
        const int r = w * 4 + rr;
        float a = 0.f;
        #pragma unroll
        for (int it = 0; it < 8; it++) {
            float4 v = *(const float4*)(S + r * SSTRIDE + it * 128 + lane * 4);
            a += v.x + v.y + v.z + v.w;
        }
        #pragma unroll
        for (int off = 16; off > 0; off >>= 1)
            a += __shfl_xor_sync(0xffffffffu, a, off);
        if (lane == 0) sums[r] = 1.0f / a;
    }
    __syncthreads();

    // ---- scale + coalesced store ----
    #pragma unroll
    for (int rr = 0; rr < 4; rr++) {
        const int r = w * 4 + rr;
        const float inv = sums[r];
        float* ob = out + (((size_t)(h * B_SZ + b) * S_LEN + i0 + r) << 10);
        #pragma unroll
        for (int it = 0; it < 8; it++) {
            float4 v = *(const float4*)(S + r * SSTRIDE + it * 128 + lane * 4);
            v.x *= inv; v.y *= inv; v.z *= inv; v.w *= inv;
            *(float4*)(ob + it * 128 + lane * 4) = v;
        }
    }
}

// ---------------- launch ----------------
extern "C" void kernel_launch(void* const* d_in, const int* in_sizes, int n_in,
                              void* d_out, int out_size) {
    const float* x        = (const float*)d_in[0];
    const float* pos_emb  = (const float*)d_in[1];
    const unsigned char* kpm = (const unsigned char*)d_in[2];
    const float* in_w     = (const float*)d_in[3];
    const float* in_b     = (const float*)d_in[4];
    const float* lpw      = (const float*)d_in[5];
    float* out = (float*)d_out;

    xsplit_kernel<<<4096, 256>>>(x);
    wsplit_kernel<<<272, 256>>>(in_w);
    {
        cudaFuncSetAttribute(pe_kernel,
                             cudaFuncAttributeMaxDynamicSharedMemorySize, PE_SMEM_BYTES);
        dim3 blk(32, 8);
        dim3 grd((NPE + PE_NB - 1) / PE_NB);
        pe_kernel<<<grd, blk, PE_SMEM_BYTES>>>(pos_emb, lpw);
    }
    {
        cudaFuncSetAttribute(proj_mma_kernel,
                             cudaFuncAttributeMaxDynamicSharedMemorySize, PJ_SMEM);
        dim3 grd((IN_PROJ + 63) / 64, 8192 / 128);
        proj_mma_kernel<<<grd, 256, PJ_SMEM>>>(in_b);
    }
    {
        cudaFuncSetAttribute(scores_kernel,
                             cudaFuncAttributeMaxDynamicSharedMemorySize, SC_SMEM);
        dim3 grd(S_LEN / 32, B_SZ, H_NUM);
        scores_kernel<<<grd, 256, SC_SMEM>>>(kpm, out);
    }
}

// round 12
// speedup vs baseline: 1.8114x; 1.4282x over previous
#include <cuda_runtime.h>
#include <cuda_bf16.h>
#include <cstdint>

#define S_LEN 1024
#define B_SZ  8
#define E_DIM 512
#define H_NUM 8
#define QHD   32
#define PHD   4
#define PDIM  192
#define IN_PROJ 544
#define NPE   2047

typedef unsigned int u32;

// ---------------- device scratch ----------------
__device__ __nv_bfloat16 g_Qs[B_SZ * H_NUM * S_LEN * 64];  // [bh][s][Qh|Ql]
__device__ __nv_bfloat16 g_Ks[B_SZ * H_NUM * S_LEN * 64];  // [bh][s][Kh|Kl]
__device__ float g_P[B_SZ * H_NUM * S_LEN * PHD];          // [bh][s][p]
__device__ float g_pe4[H_NUM * 2048 * 4];                  // [h][n][p]
__device__ __nv_bfloat16 g_Xh[8192 * E_DIM];
__device__ __nv_bfloat16 g_Xl[8192 * E_DIM];
__device__ __nv_bfloat16 g_Wh[IN_PROJ * E_DIM];
__device__ __nv_bfloat16 g_Wl[IN_PROJ * E_DIM];

__device__ __forceinline__ u32 s2u(const void* p) {
    u32 a; asm("{ .reg .u64 t; cvta.to.shared.u64 t, %1; cvt.u32.u64 %0, t; }"
               : "=r"(a) : "l"(p)); return a;
}

#define SWZ(r, c16) ((((c16) ^ ((r) & 7)) << 4))

#define LDSM_X4(a0,a1,a2,a3, addr) \
    asm volatile("ldmatrix.sync.aligned.m8n8.x4.shared.b16 {%0,%1,%2,%3}, [%4];" \
        : "=r"(a0), "=r"(a1), "=r"(a2), "=r"(a3) : "r"(addr))
#define LDSM_X2(b0,b1, addr) \
    asm volatile("ldmatrix.sync.aligned.m8n8.x2.shared.b16 {%0,%1}, [%2];" \
        : "=r"(b0), "=r"(b1) : "r"(addr))
#define MMA16816(c, a, b0, b1) \
    asm volatile("mma.sync.aligned.m16n8k16.row.col.f32.bf16.bf16.f32 " \
        "{%0,%1,%2,%3}, {%4,%5,%6,%7}, {%8,%9}, {%0,%1,%2,%3};" \
        : "+f"((c)[0]), "+f"((c)[1]), "+f"((c)[2]), "+f"((c)[3]) \
        : "r"((a)[0]), "r"((a)[1]), "r"((a)[2]), "r"((a)[3]), "r"(b0), "r"(b1))

// ---------------- split prepass kernels ----------------
__global__ void xsplit_kernel(const float* __restrict__ x) {
    size_t i = ((size_t)blockIdx.x * 256 + threadIdx.x) * 4;
    float4 v = *(const float4*)(x + i);
    __nv_bfloat16 h0 = __float2bfloat16(v.x);
    __nv_bfloat16 h1 = __float2bfloat16(v.y);
    __nv_bfloat16 h2 = __float2bfloat16(v.z);
    __nv_bfloat16 h3 = __float2bfloat16(v.w);
    __nv_bfloat162 a, b;
    a.x = h0; a.y = h1; b.x = h2; b.y = h3;
    ((__nv_bfloat162*)(g_Xh + i))[0] = a;
    ((__nv_bfloat162*)(g_Xh + i))[1] = b;
    a.x = __float2bfloat16(v.x - __bfloat162float(h0));
    a.y = __float2bfloat16(v.y - __bfloat162float(h1));
    b.x = __float2bfloat16(v.z - __bfloat162float(h2));
    b.y = __float2bfloat16(v.w - __bfloat162float(h3));
    ((__nv_bfloat162*)(g_Xl + i))[0] = a;
    ((__nv_bfloat162*)(g_Xl + i))[1] = b;
}

__global__ void wsplit_kernel(const float* __restrict__ w) {
    size_t i = ((size_t)blockIdx.x * 256 + threadIdx.x) * 4;
    float4 v = *(const float4*)(w + i);
    __nv_bfloat16 h0 = __float2bfloat16(v.x);
    __nv_bfloat16 h1 = __float2bfloat16(v.y);
    __nv_bfloat16 h2 = __float2bfloat16(v.z);
    __nv_bfloat16 h3 = __float2bfloat16(v.w);
    __nv_bfloat162 a, b;
    a.x = h0; a.y = h1; b.x = h2; b.y = h3;
    ((__nv_bfloat162*)(g_Wh + i))[0] = a;
    ((__nv_bfloat162*)(g_Wh + i))[1] = b;
    a.x = __float2bfloat16(v.x - __bfloat162float(h0));
    a.y = __float2bfloat16(v.y - __bfloat162float(h1));
    b.x = __float2bfloat16(v.z - __bfloat162float(h2));
    b.y = __float2bfloat16(v.w - __bfloat162float(h3));
    ((__nv_bfloat162*)(g_Wl + i))[0] = a;
    ((__nv_bfloat162*)(g_Wl + i))[1] = b;
}

// ---------------- pe kernel (smem-tiled) ----------------
#define PE_NB 32
#define PE_PAD 193
#define PE_WPAD 34
#define PE_SMEM_BYTES ((PE_NB * PE_PAD + PDIM * PE_WPAD) * 4)
__global__ void __launch_bounds__(256) pe_kernel(const float* __restrict__ pos_emb,
                                                 const float* __restrict__ lpw) {
    extern __shared__ __align__(128) char smem_dyn[];
    float* pesm = (float*)smem_dyn;
    float* pet = pesm;
    float* wt  = pesm + PE_NB * PE_PAD;
    const int tid = threadIdx.y * 32 + threadIdx.x;
    const int n0 = blockIdx.x * PE_NB;

    for (int idx = tid; idx < PE_NB * (PDIM / 4); idx += 256) {
        int r = idx / (PDIM / 4), c = (idx % (PDIM / 4)) * 4;
        float4 v = make_float4(0.f, 0.f, 0.f, 0.f);
        if (n0 + r < NPE) v = *(const float4*)(pos_emb + (size_t)(n0 + r) * PDIM + c);
        pet[r * PE_PAD + c + 0] = v.x;
        pet[r * PE_PAD + c + 1] = v.y;
        pet[r * PE_PAD + c + 2] = v.z;
        pet[r * PE_PAD + c + 3] = v.w;
    }
    for (int idx = tid; idx < 32 * (PDIM / 4); idx += 256) {
        int r = idx / (PDIM / 4), c = (idx % (PDIM / 4)) * 4;
        float4 v = *(const float4*)(lpw + (size_t)r * PDIM + c);
        wt[(c + 0) * PE_WPAD + r] = v.x;
        wt[(c + 1) * PE_WPAD + r] = v.y;
        wt[(c + 2) * PE_WPAD + r] = v.z;
        wt[(c + 3) * PE_WPAD + r] = v.w;
    }
    __syncthreads();

    const int x = threadIdx.x;
    const int y = threadIdx.y;
    float a0 = 0.f, a1 = 0.f, a2 = 0.f, a3 = 0.f;
    #pragma unroll 4
    for (int d = 0; d < PDIM; d++) {
        float pv = pet[x * PE_PAD + d];
        const float* wr = wt + d * PE_WPAD + y * 4;
        a0 = fmaf(pv, wr[0], a0);
        a1 = fmaf(pv, wr[1], a1);
        a2 = fmaf(pv, wr[2], a2);
        a3 = fmaf(pv, wr[3], a3);
    }
    const int n = n0 + x;
    if (n < NPE)
        ((float4*)g_pe4)[y * 2048 + n] = make_float4(a0, a1, a2, a3);
}

// ---------------- proj: HMMA bf16-split GEMM + scatter (unchanged) -------
#define PJ_XH 0
#define PJ_XL 16384
#define PJ_WH 32768
#define PJ_WL 40960
#define PJ_SMEM 49152

__device__ __forceinline__ void proj_scatter(int m, int o, float v,
                                             const float* __restrict__ bias) {
    v += bias[o];
    int seq = m >> 3, b = m & 7;
    if (o < 512) {
        int oo = o & 255;
        int h = oo >> 5, d = oo & 31;
        __nv_bfloat16 hi = __float2bfloat16(v);
        __nv_bfloat16 lo = __float2bfloat16(v - __bfloat162float(hi));
        __nv_bfloat16* dst = (o < 256 ? g_Qs : g_Ks) +
                             ((size_t)(b * H_NUM + h) * S_LEN + seq) * 64;
        dst[d] = hi;
        dst[32 + d] = lo;
    } else {
        int oo = o - 512;
        g_P[((size_t)(b * H_NUM + (oo >> 2)) * S_LEN + seq) * PHD + (oo & 3)] = v;
    }
}

__global__ void __launch_bounds__(256) proj_mma_kernel(const float* __restrict__ bias) {
    extern __shared__ __align__(128) char smem_dyn[];
    char* psm = smem_dyn;
    const u32 pb = s2u(psm);
    const int tid = threadIdx.x;
    const int w = tid >> 5, lane = tid & 31;
    const int wm = w & 3, wn = w >> 2;
    const int m0 = blockIdx.y * 128;
    const int n0 = blockIdx.x * 64;

    float acc[2][4][4];
    #pragma unroll
    for (int mt = 0; mt < 2; mt++)
        #pragma unroll
        for (int nt = 0; nt < 4; nt++)
            #pragma unroll
            for (int e = 0; e < 4; e++) acc[mt][nt][e] = 0.f;

    const int a_row = lane & 15, a_hi = (lane >> 4) & 1;
    const int b_lane = lane & 7, b_hi = (lane >> 3) & 1;

    for (int k0 = 0; k0 < E_DIM; k0 += 64) {
        for (int t = tid; t < 1024; t += 256) {
            int row = t >> 3, c16 = t & 7;
            size_t src = (size_t)(m0 + row) * E_DIM + k0 + c16 * 8;
            *(float4*)(psm + PJ_XH + row * 128 + SWZ(row, c16)) = *(const float4*)(g_Xh + src);
            *(float4*)(psm + PJ_XL + row * 128 + SWZ(row, c16)) = *(const float4*)(g_Xl + src);
        }
        for (int t = tid; t < 512; t += 256) {
            int row = t >> 3, c16 = t & 7;
            int n = n0 + row;
            float4 vh = make_float4(0.f, 0.f, 0.f, 0.f), vl = vh;
            if (n < IN_PROJ) {
                size_t src = (size_t)n * E_DIM + k0 + c16 * 8;
                vh = *(const float4*)(g_Wh + src);
                vl = *(const float4*)(g_Wl + src);
            }
            *(float4*)(psm + PJ_WH + row * 128 + SWZ(row, c16)) = vh;
            *(float4*)(psm + PJ_WL + row * 128 + SWZ(row, c16)) = vl;
        }
        __syncthreads();

        #pragma unroll
        for (int ks = 0; ks < 4; ks++) {
            u32 ah[2][4], al[2][4];
            #pragma unroll
            for (int mt = 0; mt < 2; mt++) {
                int r = wm * 32 + mt * 16 + a_row;
                LDSM_X4(ah[mt][0], ah[mt][1], ah[mt][2], ah[mt][3],
                        pb + PJ_XH + r * 128 + SWZ(r, ks * 2 + a_hi));
                LDSM_X4(al[mt][0], al[mt][1], al[mt][2], al[mt][3],
                        pb + PJ_XL + r * 128 + SWZ(r, ks * 2 + a_hi));
            }
            #pragma unroll
            for (int nt = 0; nt < 4; nt++) {
                int r = wn * 32 + nt * 8 + b_lane;
                u32 bh0, bh1, bl0, bl1;
                LDSM_X2(bh0, bh1, pb + PJ_WH + r * 128 + SWZ(r, ks * 2 + b_hi));
                LDSM_X2(bl0, bl1, pb + PJ_WL + r * 128 + SWZ(r, ks * 2 + b_hi));
                #pragma unroll
                for (int mt = 0; mt < 2; mt++) {
                    MMA16816(acc[mt][nt], ah[mt], bh0, bh1);
                    MMA16816(acc[mt][nt], al[mt], bh0, bh1);
                    MMA16816(acc[mt][nt], ah[mt], bl0, bl1);
                }
            }
        }
        __syncthreads();
    }

    const int g = lane >> 2, t2 = (lane & 3) * 2;
    #pragma unroll
    for (int mt = 0; mt < 2; mt++) {
        #pragma unroll
        for (int nt = 0; nt < 4; nt++) {
            int o0 = n0 + wn * 32 + nt * 8 + t2;
            int m1 = m0 + wm * 32 + mt * 16 + g;
            if (o0 < IN_PROJ) {
                proj_scatter(m1,     o0, acc[mt][nt][0], bias);
                proj_scatter(m1 + 8, o0, acc[mt][nt][2], bias);
            }
            if (o0 + 1 < IN_PROJ) {
                proj_scatter(m1,     o0 + 1, acc[mt][nt][1], bias);
                proj_scatter(m1 + 8, o0 + 1, acc[mt][nt][3], bias);
            }
        }
    }
}

// ---------------- scores v3: 16-row tiles, K phase-split, occ=2 -----------
// block = 16 q-rows x (b,h); 8 warps; warp w owns cols [w*128, w*128+128).
// K staged in one 64KB buffer: phase 0 = Kh (4 k-steps), phase 1 = Kl (2 steps).
// Register epilogue; staged store reuses K+Q region (exactly 67584B).
#define OFF_KB   0            // 1024 x 64B (one split half), swizzled
#define OFF_Q    65536        // 16 x 128B SW128
#define OFF_STG  0            // reuse: 8 warps x [16][132] f32 = 67584
#define OFF_PE   67584        // [1040] float4
#define OFF_MSK  84224        // [1024] u8
#define OFF_PS   85248        // [16][4] f32
#define OFF_SUM  85504        // [16] f32
#define SC_SMEM  85632

// K buffer: row r, c16 in 0..3 -> addr = r*64 + ((c16 ^ (r&3))<<4)
#define KSWZ(r, c) (((c) ^ ((r) & 3)) << 4)

__global__ void __launch_bounds__(256, 2)
scores_kernel(const unsigned char* __restrict__ mask, float* __restrict__ out) {
    extern __shared__ __align__(128) char smem_dyn[];
    char* smem = smem_dyn;
    const u32 sbase = s2u(smem);

    const int i0 = blockIdx.x * 16;
    const int b  = blockIdx.y;
    const int h  = blockIdx.z;
    const int tid = threadIdx.x;
    const size_t bh = (size_t)(b * H_NUM + h);

    const int w = tid >> 5, lane = tid & 31;
    const int jb = w * 128;
    const int g = lane >> 2, t2 = (lane & 3) * 2;

    // ---- non-K loads ----
    {
        const float4* qs = (const float4*)(g_Qs + (bh * S_LEN + i0) * 64);
        if (tid < 128) {
            int row = tid >> 3, c16 = tid & 7;
            *(float4*)(smem + OFF_Q + row * 128 + SWZ(row, c16)) = qs[tid];
        }
        const int nlo = 1008 - i0;
        const float4* peg = (const float4*)(g_pe4 + (size_t)h * 2048 * 4);
        #pragma unroll
        for (int t = tid; t < 1040; t += 256)
            ((float4*)(smem + OFF_PE))[t] = peg[nlo + t];
        ((int*)(smem + OFF_MSK))[tid] = ((const int*)(mask + (size_t)b * S_LEN))[tid];
        if (tid < 16) {
            ((float4*)(smem + OFF_PS))[tid] = ((const float4*)(g_P + (bh * S_LEN + i0) * PHD))[tid];
            ((float*)(smem + OFF_SUM))[tid] = 0.f;
        }
    }

    float acc[16][4];
    #pragma unroll
    for (int nt = 0; nt < 16; nt++)
        #pragma unroll
        for (int e = 0; e < 4; e++) acc[nt][e] = 0.f;

    const int a_row = lane & 15;
    const int a_hi  = (lane >> 4) & 1;
    const int b_row = jb + (lane & 7);
    const int b_hi  = (lane >> 3) & 1;
    const __nv_bfloat16* kg = g_Ks + bh * (size_t)S_LEN * 64;

    // ---- two K phases: 0 = Kh (4 ksteps: QhKh x2, QlKh x2), 1 = Kl (QhKl x2)
    #pragma unroll
    for (int phase = 0; phase < 2; phase++) {
        // load 64KB half: row*128B + phase*64B + c16*16B from global
        #pragma unroll
        for (int t = tid; t < 4096; t += 256) {
            int row = t >> 2, c16 = t & 3;
            float4 v = ((const float4*)kg)[row * 8 + phase * 4 + c16];
            *(float4*)(smem + OFF_KB + row * 64 + KSWZ(row, c16)) = v;
        }
        __syncthreads();

        const int nsteps = phase == 0 ? 4 : 2;
        #pragma unroll
        for (int s = 0; s < 4; s++) {
            if (s >= nsteps) break;
            const int ac = (phase == 0) ? (s * 2) : (s * 2);        // Qh c16 0/2
            const int ac2 = (phase == 0 && s >= 2) ? (s * 2) : ac;  // Ql c16 4/6
            const int acol = (phase == 0) ? ((s < 2) ? s * 2 : s * 2) : s * 2;
            // explicit: phase0 s={0,1}: A c16 {0,2} (Qh); s={2,3}: {4,6} (Ql)
            //           phase1 s={0,1}: A c16 {0,2} (Qh)
            const int a_c16 = (phase == 0) ? (s * 2) : (s * 2);
            const int b_c   = (s & 1) * 2;
            (void)ac; (void)ac2; (void)acol;

            u32 af[4];
            {
                int r = a_row;
                LDSM_X4(af[0], af[1], af[2], af[3],
                        sbase + OFF_Q + r * 128 + SWZ(r, a_c16 + a_hi));
            }
            #pragma unroll
            for (int nt = 0; nt < 16; nt++) {
                int r = b_row + nt * 8;
                u32 b0, b1;
                LDSM_X2(b0, b1, sbase + OFF_KB + r * 64 + KSWZ(r, b_c + b_hi));
                MMA16816(acc[nt], af, b0, b1);
            }
        }
        __syncthreads();
    }

    // ---- epilogue in regs: pos + mask + exp + row sums ----
    const float4* pef4 = (const float4*)(smem + OFF_PE);
    const float*  psf  = (const float*)(smem + OFF_PS);
    const unsigned char* msk = (const unsigned char*)(smem + OFF_MSK);
    float* sums = (float*)(smem + OFF_SUM);

    {
        const float4 pw1 = *(const float4*)(psf + g * 4);
        const float4 pw2 = *(const float4*)(psf + (g + 8) * 4);
        float ps1 = 0.f, ps2 = 0.f;
        #pragma unroll
        for (int nt = 0; nt < 16; nt++) {
            const int j = jb + nt * 8 + t2;
            const int idx0 = 15 - g + j;          // row g
            float4 p0 = pef4[idx0];
            float4 p1 = pef4[idx0 + 1];
            float4 p2 = pef4[idx0 - 8];           // row g+8
            float4 p3 = pef4[idx0 - 7];
            const bool m0 = msk[j], m1 = msk[j + 1];
            float s0 = acc[nt][0] + pw1.x*p0.x + pw1.y*p0.y + pw1.z*p0.z + pw1.w*p0.w;
            float s1 = acc[nt][1] + pw1.x*p1.x + pw1.y*p1.y + pw1.z*p1.z + pw1.w*p1.w;
            float s2 = acc[nt][2] + pw2.x*p2.x + pw2.y*p2.y + pw2.z*p2.z + pw2.w*p2.w;
            float s3 = acc[nt][3] + pw2.x*p3.x + pw2.y*p3.y + pw2.z*p3.z + pw2.w*p3.w;
            if (m0) { s0 = -1000.f; s2 = -1000.f; }
            if (m1) { s1 = -1000.f; s3 = -1000.f; }
            float e0 = __expf(s0), e1 = __expf(s1), e2 = __expf(s2), e3 = __expf(s3);
            acc[nt][0] = e0; acc[nt][1] = e1; acc[nt][2] = e2; acc[nt][3] = e3;
            ps1 += e0 + e1; ps2 += e2 + e3;
        }
        ps1 += __shfl_xor_sync(0xffffffffu, ps1, 1);
        ps1 += __shfl_xor_sync(0xffffffffu, ps1, 2);
        ps2 += __shfl_xor_sync(0xffffffffu, ps2, 1);
        ps2 += __shfl_xor_sync(0xffffffffu, ps2, 2);
        if ((lane & 3) == 0) {
            atomicAdd(&sums[g], ps1);
            atomicAdd(&sums[g + 8], ps2);
        }
    }
    __syncthreads();
    if (tid < 16) sums[tid] = 1.0f / sums[tid];
    __syncthreads();

    // ---- scale in regs + staged coalesced store (reuse K+Q region) ----
    const float inv1 = sums[g];
    const float inv2 = sums[g + 8];
    float* stg = (float*)(smem + OFF_STG) + w * 2112;   // [16][132]
    #pragma unroll
    for (int nt = 0; nt < 16; nt++) {
        const int c = nt * 8 + t2;
        *(float2*)(stg + g * 132 + c)       = make_float2(acc[nt][0] * inv1, acc[nt][1] * inv1);
        *(float2*)(stg + (g + 8) * 132 + c) = make_float2(acc[nt][2] * inv2, acc[nt][3] * inv2);
    }
    __syncwarp();
    float* ob = out + (((size_t)(h * B_SZ + b) * S_LEN + i0) << 10) + jb;
    #pragma unroll
    for (int it = 0; it < 16; it++) {
        float4 v = *(const float4*)(stg + it * 132 + lane * 4);
        *(float4*)(ob + ((size_t)it << 10) + lane * 4) = v;
    }
}

// ---------------- launch ----------------
extern "C" void kernel_launch(void* const* d_in, const int* in_sizes, int n_in,
                              void* d_out, int out_size) {
    const float* x        = (const float*)d_in[0];
    const float* pos_emb  = (const float*)d_in[1];
    const unsigned char* kpm = (const unsigned char*)d_in[2];
    const float* in_w     = (const float*)d_in[3];
    const float* in_b     = (const float*)d_in[4];
    const float* lpw      = (const float*)d_in[5];
    float* out = (float*)d_out;

    xsplit_kernel<<<4096, 256>>>(x);
    wsplit_kernel<<<272, 256>>>(in_w);
    {
        cudaFuncSetAttribute(pe_kernel,
                             cudaFuncAttributeMaxDynamicSharedMemorySize, PE_SMEM_BYTES);
        dim3 blk(32, 8);
        dim3 grd((NPE + PE_NB - 1) / PE_NB);
        pe_kernel<<<grd, blk, PE_SMEM_BYTES>>>(pos_emb, lpw);
    }
    {
        cudaFuncSetAttribute(proj_mma_kernel,
                             cudaFuncAttributeMaxDynamicSharedMemorySize, PJ_SMEM);
        dim3 grd((IN_PROJ + 63) / 64, 8192 / 128);
        proj_mma_kernel<<<grd, 256, PJ_SMEM>>>(in_b);
    }
    {
        cudaFuncSetAttribute(scores_kernel,
                             cudaFuncAttributeMaxDynamicSharedMemorySize, SC_SMEM);
        dim3 grd(S_LEN / 16, B_SZ, H_NUM);
        scores_kernel<<<grd, 256, SC_SMEM>>>(kpm, out);
    }
}

// round 13
// speedup vs baseline: 1.9141x; 1.0567x over previous
#include <cuda_runtime.h>
#include <cuda_bf16.h>
#include <cstdint>

#define S_LEN 1024
#define B_SZ  8
#define E_DIM 512
#define H_NUM 8
#define QHD   32
#define PHD   4
#define PDIM  192
#define IN_PROJ 544
#define NPE   2047

typedef unsigned int u32;

// ---------------- device scratch ----------------
__device__ __nv_bfloat16 g_Qs[B_SZ * H_NUM * S_LEN * 64];  // [bh][s][Qh|Ql]
__device__ __nv_bfloat16 g_Ks[B_SZ * H_NUM * S_LEN * 64];  // [bh][s][Kh|Kl]
__device__ float g_P[B_SZ * H_NUM * S_LEN * PHD];          // [bh][s][p]
__device__ float g_pe4[H_NUM * 2048 * 4];                  // [h][n][p]

__device__ __forceinline__ u32 s2u(const void* p) {
    u32 a; asm("{ .reg .u64 t; cvta.to.shared.u64 t, %1; cvt.u32.u64 %0, t; }"
               : "=r"(a) : "l"(p)); return a;
}

#define SWZ(r, c16) ((((c16) ^ ((r) & 7)) << 4))

#define LDSM_X4(a0,a1,a2,a3, addr) \
    asm volatile("ldmatrix.sync.aligned.m8n8.x4.shared.b16 {%0,%1,%2,%3}, [%4];" \
        : "=r"(a0), "=r"(a1), "=r"(a2), "=r"(a3) : "r"(addr))
#define MMA16816(c, a, b0, b1) \
    asm volatile("mma.sync.aligned.m16n8k16.row.col.f32.bf16.bf16.f32 " \
        "{%0,%1,%2,%3}, {%4,%5,%6,%7}, {%8,%9}, {%0,%1,%2,%3};" \
        : "+f"((c)[0]), "+f"((c)[1]), "+f"((c)[2]), "+f"((c)[3]) \
        : "r"((a)[0]), "r"((a)[1]), "r"((a)[2]), "r"((a)[3]), "r"(b0), "r"(b1))

// split a pair of floats into packed bf16x2 hi and lo parts
__device__ __forceinline__ void split2(float a, float b, u32& hi, u32& lo) {
    __nv_bfloat16 ha = __float2bfloat16(a), hb = __float2bfloat16(b);
    __nv_bfloat16 la = __float2bfloat16(a - __bfloat162float(ha));
    __nv_bfloat16 lb = __float2bfloat16(b - __bfloat162float(hb));
    __nv_bfloat162 H; H.x = ha; H.y = hb;
    __nv_bfloat162 L; L.x = la; L.y = lb;
    hi = *(u32*)&H; lo = *(u32*)&L;
}

// ---------------- pe kernel (smem-tiled) ----------------
#define PE_NB 32
#define PE_PAD 193
#define PE_WPAD 34
#define PE_SMEM_BYTES ((PE_NB * PE_PAD + PDIM * PE_WPAD) * 4)
__global__ void __launch_bounds__(256) pe_kernel(const float* __restrict__ pos_emb,
                                                 const float* __restrict__ lpw) {
    extern __shared__ __align__(128) char smem_dyn[];
    float* pesm = (float*)smem_dyn;
    float* pet = pesm;
    float* wt  = pesm + PE_NB * PE_PAD;
    const int tid = threadIdx.y * 32 + threadIdx.x;
    const int n0 = blockIdx.x * PE_NB;

    for (int idx = tid; idx < PE_NB * (PDIM / 4); idx += 256) {
        int r = idx / (PDIM / 4), c = (idx % (PDIM / 4)) * 4;
        float4 v = make_float4(0.f, 0.f, 0.f, 0.f);
        if (n0 + r < NPE) v = *(const float4*)(pos_emb + (size_t)(n0 + r) * PDIM + c);
        pet[r * PE_PAD + c + 0] = v.x;
        pet[r * PE_PAD + c + 1] = v.y;
        pet[r * PE_PAD + c + 2] = v.z;
        pet[r * PE_PAD + c + 3] = v.w;
    }
    for (int idx = tid; idx < 32 * (PDIM / 4); idx += 256) {
        int r = idx / (PDIM / 4), c = (idx % (PDIM / 4)) * 4;
        float4 v = *(const float4*)(lpw + (size_t)r * PDIM + c);
        wt[(c + 0) * PE_WPAD + r] = v.x;
        wt[(c + 1) * PE_WPAD + r] = v.y;
        wt[(c + 2) * PE_WPAD + r] = v.z;
        wt[(c + 3) * PE_WPAD + r] = v.w;
    }
    __syncthreads();

    const int x = threadIdx.x;
    const int y = threadIdx.y;
    float a0 = 0.f, a1 = 0.f, a2 = 0.f, a3 = 0.f;
    #pragma unroll 4
    for (int d = 0; d < PDIM; d++) {
        float pv = pet[x * PE_PAD + d];
        const float* wr = wt + d * PE_WPAD + y * 4;
        a0 = fmaf(pv, wr[0], a0);
        a1 = fmaf(pv, wr[1], a1);
        a2 = fmaf(pv, wr[2], a2);
        a3 = fmaf(pv, wr[3], a3);
    }
    const int n = n0 + x;
    if (n < NPE)
        ((float4*)g_pe4)[y * 2048 + n] = make_float4(a0, a1, a2, a3);
}

// ---------------- proj v2: BM=256, fused split, LDSM_X4 B-pairing --------
// C[8192][544] = X[8192][512] @ W^T.  block 256x64, 8 warps (wm 0..3 x wn 0..1),
// warp tile 64x32.  In-kernel fp32 -> bf16 hi/lo split on tile load.
#define PJ_XH 0
#define PJ_XL 32768
#define PJ_WH 65536
#define PJ_WL 73728
#define PJ_SMEM 81920

__device__ __forceinline__ void proj_scatter(int m, int o, float v,
                                             const float* __restrict__ bias) {
    v += bias[o];
    int seq = m >> 3, b = m & 7;
    if (o < 512) {
        int oo = o & 255;
        int h = oo >> 5, d = oo & 31;
        __nv_bfloat16 hi = __float2bfloat16(v);
        __nv_bfloat16 lo = __float2bfloat16(v - __bfloat162float(hi));
        __nv_bfloat16* dst = (o < 256 ? g_Qs : g_Ks) +
                             ((size_t)(b * H_NUM + h) * S_LEN + seq) * 64;
        dst[d] = hi;
        dst[32 + d] = lo;
    } else {
        int oo = o - 512;
        g_P[((size_t)(b * H_NUM + (oo >> 2)) * S_LEN + seq) * PHD + (oo & 3)] = v;
    }
}

__global__ void __launch_bounds__(256, 2)
proj_mma_kernel(const float* __restrict__ x, const float* __restrict__ wmat,
                const float* __restrict__ bias) {
    extern __shared__ __align__(128) char smem_dyn[];
    char* psm = smem_dyn;
    const u32 pb = s2u(psm);
    const int tid = threadIdx.x;
    const int w = tid >> 5, lane = tid & 31;
    const int wm = w >> 1, wn = w & 1;
    const int m0 = blockIdx.y * 256;
    const int n0 = blockIdx.x * 64;

    float acc[4][4][4];
    #pragma unroll
    for (int mt = 0; mt < 4; mt++)
        #pragma unroll
        for (int nt = 0; nt < 4; nt++)
            #pragma unroll
            for (int e = 0; e < 4; e++) acc[mt][nt][e] = 0.f;

    const int a_row = lane & 15, a_hi = (lane >> 4) & 1;
    const int bmat = lane >> 3;               // 0..3 for B ldsm.x4 pairing
    const int brow = lane & 7;

    for (int k0 = 0; k0 < E_DIM; k0 += 64) {
        // X tile: 256 rows x 64 cols, fp32 -> split bf16
        #pragma unroll
        for (int t = tid; t < 2048; t += 256) {
            int row = t >> 3, c16 = t & 7;
            const float4* src = (const float4*)(x + (size_t)(m0 + row) * E_DIM + k0 + c16 * 8);
            float4 v0 = src[0], v1 = src[1];
            uint4 H, L;
            split2(v0.x, v0.y, H.x, L.x);
            split2(v0.z, v0.w, H.y, L.y);
            split2(v1.x, v1.y, H.z, L.z);
            split2(v1.z, v1.w, H.w, L.w);
            *(uint4*)(psm + PJ_XH + row * 128 + SWZ(row, c16)) = H;
            *(uint4*)(psm + PJ_XL + row * 128 + SWZ(row, c16)) = L;
        }
        // W tile: 64 rows x 64 cols
        #pragma unroll
        for (int t = tid; t < 512; t += 256) {
            int row = t >> 3, c16 = t & 7;
            int n = n0 + row;
            uint4 H = make_uint4(0u, 0u, 0u, 0u), L = H;
            if (n < IN_PROJ) {
                const float4* src = (const float4*)(wmat + (size_t)n * E_DIM + k0 + c16 * 8);
                float4 v0 = src[0], v1 = src[1];
                split2(v0.x, v0.y, H.x, L.x);
                split2(v0.z, v0.w, H.y, L.y);
                split2(v1.x, v1.y, H.z, L.z);
                split2(v1.z, v1.w, H.w, L.w);
            }
            *(uint4*)(psm + PJ_WH + row * 128 + SWZ(row, c16)) = H;
            *(uint4*)(psm + PJ_WL + row * 128 + SWZ(row, c16)) = L;
        }
        __syncthreads();

        #pragma unroll
        for (int ks = 0; ks < 4; ks++) {
            u32 ah[4][4], al[4][4];
            #pragma unroll
            for (int mt = 0; mt < 4; mt++) {
                int r = wm * 64 + mt * 16 + a_row;
                LDSM_X4(ah[mt][0], ah[mt][1], ah[mt][2], ah[mt][3],
                        pb + PJ_XH + r * 128 + SWZ(r, ks * 2 + a_hi));
                LDSM_X4(al[mt][0], al[mt][1], al[mt][2], al[mt][3],
                        pb + PJ_XL + r * 128 + SWZ(r, ks * 2 + a_hi));
            }
            #pragma unroll
            for (int nt = 0; nt < 4; nt += 2) {
                // ldsm.x4 pairing: matrices (nt,c),(nt,c+1),(nt+1,c),(nt+1,c+1)
                int ntt = nt + (bmat >> 1);
                int cc = ks * 2 + (bmat & 1);
                int r = wn * 32 + ntt * 8 + brow;
                u32 bh0, bh1, bh2, bh3, bl0, bl1, bl2, bl3;
                LDSM_X4(bh0, bh1, bh2, bh3, pb + PJ_WH + r * 128 + SWZ(r, cc));
                LDSM_X4(bl0, bl1, bl2, bl3, pb + PJ_WL + r * 128 + SWZ(r, cc));
                #pragma unroll
                for (int mt = 0; mt < 4; mt++) {
                    MMA16816(acc[mt][nt],     ah[mt], bh0, bh1);
                    MMA16816(acc[mt][nt],     al[mt], bh0, bh1);
                    MMA16816(acc[mt][nt],     ah[mt], bl0, bl1);
                    MMA16816(acc[mt][nt + 1], ah[mt], bh2, bh3);
                    MMA16816(acc[mt][nt + 1], al[mt], bh2, bh3);
                    MMA16816(acc[mt][nt + 1], ah[mt], bl2, bl3);
                }
            }
        }
        __syncthreads();
    }

    const int g = lane >> 2, t2 = (lane & 3) * 2;
    #pragma unroll
    for (int mt = 0; mt < 4; mt++) {
        #pragma unroll
        for (int nt = 0; nt < 4; nt++) {
            int o0 = n0 + wn * 32 + nt * 8 + t2;
            int m1 = m0 + wm * 64 + mt * 16 + g;
            if (o0 < IN_PROJ) {
                proj_scatter(m1,     o0, acc[mt][nt][0], bias);
                proj_scatter(m1 + 8, o0, acc[mt][nt][2], bias);
            }
            if (o0 + 1 < IN_PROJ) {
                proj_scatter(m1,     o0 + 1, acc[mt][nt][1], bias);
                proj_scatter(m1 + 8, o0 + 1, acc[mt][nt][3], bias);
            }
        }
    }
}

// ---------------- scores: 16-row tiles, K phase-split, occ=2, B ldsm.x4 ---
#define OFF_KB   0            // 1024 x 64B (one split half), swizzled
#define OFF_Q    65536        // 16 x 128B SW128
#define OFF_STG  0            // reuse: 8 warps x [16][132] f32 = 67584
#define OFF_PE   67584        // [1040] float4
#define OFF_MSK  84224        // [1024] u8
#define OFF_PS   85248        // [16][4] f32
#define OFF_SUM  85504        // [16] f32
#define SC_SMEM  85632

#define KSWZ(r, c) ((((c) ^ ((r) & 3)) << 4))

__global__ void __launch_bounds__(256, 2)
scores_kernel(const unsigned char* __restrict__ mask, float* __restrict__ out) {
    extern __shared__ __align__(128) char smem_dyn[];
    char* smem = smem_dyn;
    const u32 sbase = s2u(smem);

    const int i0 = blockIdx.x * 16;
    const int b  = blockIdx.y;
    const int h  = blockIdx.z;
    const int tid = threadIdx.x;
    const size_t bh = (size_t)(b * H_NUM + h);

    const int w = tid >> 5, lane = tid & 31;
    const int jb = w * 128;
    const int g = lane >> 2, t2 = (lane & 3) * 2;

    // ---- non-K loads ----
    {
        const float4* qs = (const float4*)(g_Qs + (bh * S_LEN + i0) * 64);
        if (tid < 128) {
            int row = tid >> 3, c16 = tid & 7;
            *(float4*)(smem + OFF_Q + row * 128 + SWZ(row, c16)) = qs[tid];
        }
        const int nlo = 1008 - i0;
        const float4* peg = (const float4*)(g_pe4 + (size_t)h * 2048 * 4);
        #pragma unroll
        for (int t = tid; t < 1040; t += 256)
            ((float4*)(smem + OFF_PE))[t] = peg[nlo + t];
        ((int*)(smem + OFF_MSK))[tid] = ((const int*)(mask + (size_t)b * S_LEN))[tid];
        if (tid < 16) {
            ((float4*)(smem + OFF_PS))[tid] = ((const float4*)(g_P + (bh * S_LEN + i0) * PHD))[tid];
            ((float*)(smem + OFF_SUM))[tid] = 0.f;
        }
    }

    float acc[16][4];
    #pragma unroll
    for (int nt = 0; nt < 16; nt++)
        #pragma unroll
        for (int e = 0; e < 4; e++) acc[nt][e] = 0.f;

    const int a_row = lane & 15;
    const int a_hi  = (lane >> 4) & 1;
    const int bmat  = lane >> 3;
    const int brow  = lane & 7;
    const __nv_bfloat16* kg = g_Ks + bh * (size_t)S_LEN * 64;

    // ---- two K phases: 0 = Kh (QhKh x2, QlKh x2), 1 = Kl (QhKl x2) ----
    #pragma unroll
    for (int phase = 0; phase < 2; phase++) {
        #pragma unroll
        for (int t = tid; t < 4096; t += 256) {
            int row = t >> 2, c16 = t & 3;
            float4 v = ((const float4*)kg)[row * 8 + phase * 4 + c16];
            *(float4*)(smem + OFF_KB + row * 64 + KSWZ(row, c16)) = v;
        }
        __syncthreads();

        const int nsteps = (phase == 0) ? 4 : 2;
        for (int s = 0; s < nsteps; s++) {
            const int a_c16 = s * 2;          // phase0: 0,2,4,6 ; phase1: 0,2
            const int b_c   = (s & 1) * 2;    // Kh/Kl buffer k-halves

            u32 af[4];
            LDSM_X4(af[0], af[1], af[2], af[3],
                    sbase + OFF_Q + a_row * 128 + SWZ(a_row, a_c16 + a_hi));
            #pragma unroll
            for (int nt = 0; nt < 16; nt += 2) {
                int ntt = nt + (bmat >> 1);
                int cc = b_c + (bmat & 1);
                int r = jb + ntt * 8 + brow;
                u32 b0, b1, b2, b3;
                LDSM_X4(b0, b1, b2, b3, sbase + OFF_KB + r * 64 + KSWZ(r, cc));
                MMA16816(acc[nt],     af, b0, b1);
                MMA16816(acc[nt + 1], af, b2, b3);
            }
        }
        __syncthreads();
    }

    // ---- epilogue in regs: pos + mask + exp + row sums ----
    const float4* pef4 = (const float4*)(smem + OFF_PE);
    const float*  psf  = (const float*)(smem + OFF_PS);
    const unsigned char* msk = (const unsigned char*)(smem + OFF_MSK);
    float* sums = (float*)(smem + OFF_SUM);

    {
        const float4 pw1 = *(const float4*)(psf + g * 4);
        const float4 pw2 = *(const float4*)(psf + (g + 8) * 4);
        float ps1 = 0.f, ps2 = 0.f;
        #pragma unroll
        for (int nt = 0; nt < 16; nt++) {
            const int j = jb + nt * 8 + t2;
            const int idx0 = 15 - g + j;
            float4 p0 = pef4[idx0];
            float4 p1 = pef4[idx0 + 1];
            float4 p2 = pef4[idx0 - 8];
            float4 p3 = pef4[idx0 - 7];
            const bool m0 = msk[j], m1 = msk[j + 1];
            float s0 = acc[nt][0] + pw1.x*p0.x + pw1.y*p0.y + pw1.z*p0.z + pw1.w*p0.w;
            float s1 = acc[nt][1] + pw1.x*p1.x + pw1.y*p1.y + pw1.z*p1.z + pw1.w*p1.w;
            float s2 = acc[nt][2] + pw2.x*p2.x + pw2.y*p2.y + pw2.z*p2.z + pw2.w*p2.w;
            float s3 = acc[nt][3] + pw2.x*p3.x + pw2.y*p3.y + pw2.z*p3.z + pw2.w*p3.w;
            if (m0) { s0 = -1000.f; s2 = -1000.f; }
            if (m1) { s1 = -1000.f; s3 = -1000.f; }
            float e0 = __expf(s0), e1 = __expf(s1), e2 = __expf(s2), e3 = __expf(s3);
            acc[nt][0] = e0; acc[nt][1] = e1; acc[nt][2] = e2; acc[nt][3] = e3;
            ps1 += e0 + e1; ps2 += e2 + e3;
        }
        ps1 += __shfl_xor_sync(0xffffffffu, ps1, 1);
        ps1 += __shfl_xor_sync(0xffffffffu, ps1, 2);
        ps2 += __shfl_xor_sync(0xffffffffu, ps2, 1);
        ps2 += __shfl_xor_sync(0xffffffffu, ps2, 2);
        if ((lane & 3) == 0) {
            atomicAdd(&sums[g], ps1);
            atomicAdd(&sums[g + 8], ps2);
        }
    }
    __syncthreads();
    if (tid < 16) sums[tid] = 1.0f / sums[tid];
    __syncthreads();

    // ---- scale in regs + staged coalesced store (reuse K+Q region) ----
    const float inv1 = sums[g];
    const float inv2 = sums[g + 8];
    float* stg = (float*)(smem + OFF_STG) + w * 2112;   // [16][132]
    #pragma unroll
    for (int nt = 0; nt < 16; nt++) {
        const int c = nt * 8 + t2;
        *(float2*)(stg + g * 132 + c)       = make_float2(acc[nt][0] * inv1, acc[nt][1] * inv1);
        *(float2*)(stg + (g + 8) * 132 + c) = make_float2(acc[nt][2] * inv2, acc[nt][3] * inv2);
    }
    __syncwarp();
    float* ob = out + (((size_t)(h * B_SZ + b) * S_LEN + i0) << 10) + jb;
    #pragma unroll
    for (int it = 0; it < 16; it++) {
        float4 v = *(const float4*)(stg + it * 132 + lane * 4);
        *(float4*)(ob + ((size_t)it << 10) + lane * 4) = v;
    }
}

// ---------------- launch ----------------
extern "C" void kernel_launch(void* const* d_in, const int* in_sizes, int n_in,
                              void* d_out, int out_size) {
    const float* x        = (const float*)d_in[0];
    const float* pos_emb  = (const float*)d_in[1];
    const unsigned char* kpm = (const unsigned char*)d_in[2];
    const float* in_w     = (const float*)d_in[3];
    const float* in_b     = (const float*)d_in[4];
    const float* lpw      = (const float*)d_in[5];
    float* out = (float*)d_out;

    {
        cudaFuncSetAttribute(pe_kernel,
                             cudaFuncAttributeMaxDynamicSharedMemorySize, PE_SMEM_BYTES);
        dim3 blk(32, 8);
        dim3 grd((NPE + PE_NB - 1) / PE_NB);
        pe_kernel<<<grd, blk, PE_SMEM_BYTES>>>(pos_emb, lpw);
    }
    {
        cudaFuncSetAttribute(proj_mma_kernel,
                             cudaFuncAttributeMaxDynamicSharedMemorySize, PJ_SMEM);
        dim3 grd((IN_PROJ + 63) / 64, 8192 / 256);
        proj_mma_kernel<<<grd, 256, PJ_SMEM>>>(x, in_w, in_b);
    }
    {
        cudaFuncSetAttribute(scores_kernel,
                             cudaFuncAttributeMaxDynamicSharedMemorySize, SC_SMEM);
        dim3 grd(S_LEN / 16, B_SZ, H_NUM);
        scores_kernel<<<grd, 256, SC_SMEM>>>(kpm, out);
    }
}

// round 15
// speedup vs baseline: 2.0185x; 1.0545x over previous
#include <cuda_runtime.h>
#include <cuda_bf16.h>
#include <cstdint>

#define S_LEN 1024
#define B_SZ  8
#define E_DIM 512
#define H_NUM 8
#define QHD   32
#define PHD   4
#define PDIM  192
#define IN_PROJ 544
#define NPE   2047

typedef unsigned int u32;

// ---------------- device scratch ----------------
__device__ __nv_bfloat16 g_Qs[B_SZ * H_NUM * S_LEN * 64];  // [bh][s][Qh|Ql]
__device__ __nv_bfloat16 g_Ks[B_SZ * H_NUM * S_LEN * 64];  // [bh][s][Kh|Kl]
__device__ float g_P[B_SZ * H_NUM * S_LEN * PHD];          // [bh][s][p]
__device__ float g_pe4[H_NUM * 2048 * 4];                  // [h][n][p]

__device__ __forceinline__ u32 s2u(const void* p) {
    u32 a; asm("{ .reg .u64 t; cvta.to.shared.u64 t, %1; cvt.u32.u64 %0, t; }"
               : "=r"(a) : "l"(p)); return a;
}

#define SWZ(r, c16) ((((c16) ^ ((r) & 7)) << 4))

#define LDSM_X4(a0,a1,a2,a3, addr) \
    asm volatile("ldmatrix.sync.aligned.m8n8.x4.shared.b16 {%0,%1,%2,%3}, [%4];" \
        : "=r"(a0), "=r"(a1), "=r"(a2), "=r"(a3) : "r"(addr))
#define MMA16816(c, a, b0, b1) \
    asm volatile("mma.sync.aligned.m16n8k16.row.col.f32.bf16.bf16.f32 " \
        "{%0,%1,%2,%3}, {%4,%5,%6,%7}, {%8,%9}, {%0,%1,%2,%3};" \
        : "+f"((c)[0]), "+f"((c)[1]), "+f"((c)[2]), "+f"((c)[3]) \
        : "r"((a)[0]), "r"((a)[1]), "r"((a)[2]), "r"((a)[3]), "r"(b0), "r"(b1))

__device__ __forceinline__ void split2(float a, float b, u32& hi, u32& lo) {
    __nv_bfloat16 ha = __float2bfloat16(a), hb = __float2bfloat16(b);
    __nv_bfloat16 la = __float2bfloat16(a - __bfloat162float(ha));
    __nv_bfloat16 lb = __float2bfloat16(b - __bfloat162float(hb));
    __nv_bfloat162 H; H.x = ha; H.y = hb;
    __nv_bfloat162 L; L.x = la; L.y = lb;
    hi = *(u32*)&H; lo = *(u32*)&L;
}

// ---------------- pe kernel (smem-tiled) ----------------
#define PE_NB 32
#define PE_PAD 193
#define PE_WPAD 34
#define PE_SMEM_BYTES ((PE_NB * PE_PAD + PDIM * PE_WPAD) * 4)
__global__ void __launch_bounds__(256) pe_kernel(const float* __restrict__ pos_emb,
                                                 const float* __restrict__ lpw) {
    extern __shared__ __align__(128) char smem_dyn[];
    float* pesm = (float*)smem_dyn;
    float* pet = pesm;
    float* wt  = pesm + PE_NB * PE_PAD;
    const int tid = threadIdx.y * 32 + threadIdx.x;
    const int n0 = blockIdx.x * PE_NB;

    for (int idx = tid; idx < PE_NB * (PDIM / 4); idx += 256) {
        int r = idx / (PDIM / 4), c = (idx % (PDIM / 4)) * 4;
        float4 v = make_float4(0.f, 0.f, 0.f, 0.f);
        if (n0 + r < NPE) v = *(const float4*)(pos_emb + (size_t)(n0 + r) * PDIM + c);
        pet[r * PE_PAD + c + 0] = v.x;
        pet[r * PE_PAD + c + 1] = v.y;
        pet[r * PE_PAD + c + 2] = v.z;
        pet[r * PE_PAD + c + 3] = v.w;
    }
    for (int idx = tid; idx < 32 * (PDIM / 4); idx += 256) {
        int r = idx / (PDIM / 4), c = (idx % (PDIM / 4)) * 4;
        float4 v = *(const float4*)(lpw + (size_t)r * PDIM + c);
        wt[(c + 0) * PE_WPAD + r] = v.x;
        wt[(c + 1) * PE_WPAD + r] = v.y;
        wt[(c + 2) * PE_WPAD + r] = v.z;
        wt[(c + 3) * PE_WPAD + r] = v.w;
    }
    __syncthreads();

    const int x = threadIdx.x;
    const int y = threadIdx.y;
    float a0 = 0.f, a1 = 0.f, a2 = 0.f, a3 = 0.f;
    #pragma unroll 4
    for (int d = 0; d < PDIM; d++) {
        float pv = pet[x * PE_PAD + d];
        const float* wr = wt + d * PE_WPAD + y * 4;
        a0 = fmaf(pv, wr[0], a0);
        a1 = fmaf(pv, wr[1], a1);
        a2 = fmaf(pv, wr[2], a2);
        a3 = fmaf(pv, wr[3], a3);
    }
    const int n = n0 + x;
    if (n < NPE)
        ((float4*)g_pe4)[y * 2048 + n] = make_float4(a0, a1, a2, a3);
}

// ---------------- proj v2: BM=256, fused split, LDSM_X4 B-pairing --------
#define PJ_XH 0
#define PJ_XL 32768
#define PJ_WH 65536
#define PJ_WL 73728
#define PJ_SMEM 81920

__device__ __forceinline__ void proj_scatter(int m, int o, float v,
                                             const float* __restrict__ bias) {
    v += bias[o];
    int seq = m >> 3, b = m & 7;
    if (o < 512) {
        int oo = o & 255;
        int h = oo >> 5, d = oo & 31;
        __nv_bfloat16 hi = __float2bfloat16(v);
        __nv_bfloat16 lo = __float2bfloat16(v - __bfloat162float(hi));
        __nv_bfloat16* dst = (o < 256 ? g_Qs : g_Ks) +
                             ((size_t)(b * H_NUM + h) * S_LEN + seq) * 64;
        dst[d] = hi;
        dst[32 + d] = lo;
    } else {
        int oo = o - 512;
        g_P[((size_t)(b * H_NUM + (oo >> 2)) * S_LEN + seq) * PHD + (oo & 3)] = v;
    }
}

__global__ void __launch_bounds__(256, 2)
proj_mma_kernel(const float* __restrict__ x, const float* __restrict__ wmat,
                const float* __restrict__ bias) {
    extern __shared__ __align__(128) char smem_dyn[];
    char* psm = smem_dyn;
    const u32 pb = s2u(psm);
    const int tid = threadIdx.x;
    const int w = tid >> 5, lane = tid & 31;
    const int wm = w >> 1, wn = w & 1;
    const int m0 = blockIdx.y * 256;
    const int n0 = blockIdx.x * 64;

    float acc[4][4][4];
    #pragma unroll
    for (int mt = 0; mt < 4; mt++)
        #pragma unroll
        for (int nt = 0; nt < 4; nt++)
            #pragma unroll
            for (int e = 0; e < 4; e++) acc[mt][nt][e] = 0.f;

    const int a_row = lane & 15, a_hi = (lane >> 4) & 1;
    const int bmat = lane >> 3;
    const int brow = lane & 7;

    for (int k0 = 0; k0 < E_DIM; k0 += 64) {
        #pragma unroll
        for (int t = tid; t < 2048; t += 256) {
            int row = t >> 3, c16 = t & 7;
            const float4* src = (const float4*)(x + (size_t)(m0 + row) * E_DIM + k0 + c16 * 8);
            float4 v0 = src[0], v1 = src[1];
            uint4 H, L;
            split2(v0.x, v0.y, H.x, L.x);
            split2(v0.z, v0.w, H.y, L.y);
            split2(v1.x, v1.y, H.z, L.z);
            split2(v1.z, v1.w, H.w, L.w);
            *(uint4*)(psm + PJ_XH + row * 128 + SWZ(row, c16)) = H;
            *(uint4*)(psm + PJ_XL + row * 128 + SWZ(row, c16)) = L;
        }
        #pragma unroll
        for (int t = tid; t < 512; t += 256) {
            int row = t >> 3, c16 = t & 7;
            int n = n0 + row;
            uint4 H = make_uint4(0u, 0u, 0u, 0u), L = H;
            if (n < IN_PROJ) {
                const float4* src = (const float4*)(wmat + (size_t)n * E_DIM + k0 + c16 * 8);
                float4 v0 = src[0], v1 = src[1];
                split2(v0.x, v0.y, H.x, L.x);
                split2(v0.z, v0.w, H.y, L.y);
                split2(v1.x, v1.y, H.z, L.z);
                split2(v1.z, v1.w, H.w, L.w);
            }
            *(uint4*)(psm + PJ_WH + row * 128 + SWZ(row, c16)) = H;
            *(uint4*)(psm + PJ_WL + row * 128 + SWZ(row, c16)) = L;
        }
        __syncthreads();

        #pragma unroll
        for (int ks = 0; ks < 4; ks++) {
            u32 ah[4][4], al[4][4];
            #pragma unroll
            for (int mt = 0; mt < 4; mt++) {
                int r = wm * 64 + mt * 16 + a_row;
                LDSM_X4(ah[mt][0], ah[mt][1], ah[mt][2], ah[mt][3],
                        pb + PJ_XH + r * 128 + SWZ(r, ks * 2 + a_hi));
                LDSM_X4(al[mt][0], al[mt][1], al[mt][2], al[mt][3],
                        pb + PJ_XL + r * 128 + SWZ(r, ks * 2 + a_hi));
            }
            #pragma unroll
            for (int nt = 0; nt < 4; nt += 2) {
                int ntt = nt + (bmat >> 1);
                int cc = ks * 2 + (bmat & 1);
                int r = wn * 32 + ntt * 8 + brow;
                u32 bh0, bh1, bh2, bh3, bl0, bl1, bl2, bl3;
                LDSM_X4(bh0, bh1, bh2, bh3, pb + PJ_WH + r * 128 + SWZ(r, cc));
                LDSM_X4(bl0, bl1, bl2, bl3, pb + PJ_WL + r * 128 + SWZ(r, cc));
                #pragma unroll
                for (int mt = 0; mt < 4; mt++) {
                    MMA16816(acc[mt][nt],     ah[mt], bh0, bh1);
                    MMA16816(acc[mt][nt],     al[mt], bh0, bh1);
                    MMA16816(acc[mt][nt],     ah[mt], bl0, bl1);
                    MMA16816(acc[mt][nt + 1], ah[mt], bh2, bh3);
                    MMA16816(acc[mt][nt + 1], al[mt], bh2, bh3);
                    MMA16816(acc[mt][nt + 1], ah[mt], bl2, bl3);
                }
            }
        }
        __syncthreads();
    }

    const int g = lane >> 2, t2 = (lane & 3) * 2;
    #pragma unroll
    for (int mt = 0; mt < 4; mt++) {
        #pragma unroll
        for (int nt = 0; nt < 4; nt++) {
            int o0 = n0 + wn * 32 + nt * 8 + t2;
            int m1 = m0 + wm * 64 + mt * 16 + g;
            if (o0 < IN_PROJ) {
                proj_scatter(m1,     o0, acc[mt][nt][0], bias);
                proj_scatter(m1 + 8, o0, acc[mt][nt][2], bias);
            }
            if (o0 + 1 < IN_PROJ) {
                proj_scatter(m1,     o0 + 1, acc[mt][nt][1], bias);
                proj_scatter(m1 + 8, o0 + 1, acc[mt][nt][3], bias);
            }
        }
    }
}

// ---------------- scores v4: B-frag sharing, pe reuse, direct stores ------
#define OFF_KB   0            // 1024 x 64B (one split half), swizzled
#define OFF_Q    65536        // 16 x 128B SW128
#define OFF_PE   67584        // [1040] float4
#define OFF_MSK  84224        // [1024] u8
#define OFF_PS   85248        // [16][4] f32
#define OFF_SUM  85504        // [16] f32
#define SC_SMEM  85632

#define KSWZ(r, c) ((((c) ^ ((r) & 3)) << 4))

__global__ void __launch_bounds__(256, 2)
scores_kernel(const unsigned char* __restrict__ mask, float* __restrict__ out) {
    extern __shared__ __align__(128) char smem_dyn[];
    char* smem = smem_dyn;
    const u32 sbase = s2u(smem);

    const int i0 = blockIdx.x * 16;
    const int b  = blockIdx.y;
    const int h  = blockIdx.z;
    const int tid = threadIdx.x;
    const size_t bh = (size_t)(b * H_NUM + h);

    const int w = tid >> 5, lane = tid & 31;
    const int jb = w * 128;
    const int g = lane >> 2, t2 = (lane & 3) * 2;

    // ---- non-K loads ----
    {
        const float4* qs = (const float4*)(g_Qs + (bh * S_LEN + i0) * 64);
        if (tid < 128) {
            int row = tid >> 3, c16 = tid & 7;
            *(float4*)(smem + OFF_Q + row * 128 + SWZ(row, c16)) = qs[tid];
        }
        const int nlo = 1008 - i0;
        const float4* peg = (const float4*)(g_pe4 + (size_t)h * 2048 * 4);
        #pragma unroll
        for (int t = tid; t < 1040; t += 256)
            ((float4*)(smem + OFF_PE))[t] = peg[nlo + t];
        ((int*)(smem + OFF_MSK))[tid] = ((const int*)(mask + (size_t)b * S_LEN))[tid];
        if (tid < 16) {
            ((float4*)(smem + OFF_PS))[tid] = ((const float4*)(g_P + (bh * S_LEN + i0) * PHD))[tid];
            ((float*)(smem + OFF_SUM))[tid] = 0.f;
        }
    }

    float acc[16][4];
    #pragma unroll
    for (int nt = 0; nt < 16; nt++)
        #pragma unroll
        for (int e = 0; e < 4; e++) acc[nt][e] = 0.f;

    const int a_row = lane & 15;
    const int a_hi  = (lane >> 4) & 1;
    const int bmat  = lane >> 3;
    const int brow  = lane & 7;
    const __nv_bfloat16* kg = g_Ks + bh * (size_t)S_LEN * 64;

    // ---- phase 0: Kh. Share B frags between Qh and Ql products ----
    {
        #pragma unroll
        for (int t = tid; t < 4096; t += 256) {
            int row = t >> 2, c16 = t & 3;
            float4 v = ((const float4*)kg)[row * 8 + c16];
            *(float4*)(smem + OFF_KB + row * 64 + KSWZ(row, c16)) = v;
        }
        __syncthreads();

        #pragma unroll
        for (int kk = 0; kk < 2; kk++) {
            u32 afh[4], afl[4];
            LDSM_X4(afh[0], afh[1], afh[2], afh[3],
                    sbase + OFF_Q + a_row * 128 + SWZ(a_row, kk * 2 + a_hi));
            LDSM_X4(afl[0], afl[1], afl[2], afl[3],
                    sbase + OFF_Q + a_row * 128 + SWZ(a_row, kk * 2 + 4 + a_hi));
            #pragma unroll
            for (int nt = 0; nt < 16; nt += 2) {
                int ntt = nt + (bmat >> 1);
                int cc = kk * 2 + (bmat & 1);
                int r = jb + ntt * 8 + brow;
                u32 b0, b1, b2, b3;
                LDSM_X4(b0, b1, b2, b3, sbase + OFF_KB + r * 64 + KSWZ(r, cc));
                MMA16816(acc[nt],     afh, b0, b1);
                MMA16816(acc[nt],     afl, b0, b1);
                MMA16816(acc[nt + 1], afh, b2, b3);
                MMA16816(acc[nt + 1], afl, b2, b3);
            }
        }
        __syncthreads();
    }
    // ---- phase 1: Kl. Qh only ----
    {
        #pragma unroll
        for (int t = tid; t < 4096; t += 256) {
            int row = t >> 2, c16 = t & 3;
            float4 v = ((const float4*)kg)[row * 8 + 4 + c16];
            *(float4*)(smem + OFF_KB + row * 64 + KSWZ(row, c16)) = v;
        }
        __syncthreads();

        #pragma unroll
        for (int kk = 0; kk < 2; kk++) {
            u32 af[4];
            LDSM_X4(af[0], af[1], af[2], af[3],
                    sbase + OFF_Q + a_row * 128 + SWZ(a_row, kk * 2 + a_hi));
            #pragma unroll
            for (int nt = 0; nt < 16; nt += 2) {
                int ntt = nt + (bmat >> 1);
                int cc = kk * 2 + (bmat & 1);
                int r = jb + ntt * 8 + brow;
                u32 b0, b1, b2, b3;
                LDSM_X4(b0, b1, b2, b3, sbase + OFF_KB + r * 64 + KSWZ(r, cc));
                MMA16816(acc[nt],     af, b0, b1);
                MMA16816(acc[nt + 1], af, b2, b3);
            }
        }
    }

    // ---- epilogue in regs: pos + mask + exp + row sums (pe reuse) ----
    const float4* pef4 = (const float4*)(smem + OFF_PE);
    const float*  psf  = (const float*)(smem + OFF_PS);
    const unsigned char* msk = (const unsigned char*)(smem + OFF_MSK);
    float* sums = (float*)(smem + OFF_SUM);

    {
        const float4 pw1 = *(const float4*)(psf + g * 4);
        const float4 pw2 = *(const float4*)(psf + (g + 8) * 4);
        float ps1 = 0.f, ps2 = 0.f;
        // prologue: p2/p3 for nt=0 are p0/p1 of "nt=-1"
        const int base0 = 15 - g + jb + t2;       // idx0 at nt=0
        float4 pprev0 = pef4[base0 - 8];
        float4 pprev1 = pef4[base0 - 7];
        #pragma unroll
        for (int nt = 0; nt < 16; nt++) {
            const int j = jb + nt * 8 + t2;
            const int idx0 = base0 + nt * 8;
            float4 p0 = pef4[idx0];
            float4 p1 = pef4[idx0 + 1];
            const bool m0 = msk[j], m1 = msk[j + 1];
            float s0 = acc[nt][0] + pw1.x*p0.x + pw1.y*p0.y + pw1.z*p0.z + pw1.w*p0.w;
            float s1 = acc[nt][1] + pw1.x*p1.x + pw1.y*p1.y + pw1.z*p1.z + pw1.w*p1.w;
            float s2 = acc[nt][2] + pw2.x*pprev0.x + pw2.y*pprev0.y + pw2.z*pprev0.z + pw2.w*pprev0.w;
            float s3 = acc[nt][3] + pw2.x*pprev1.x + pw2.y*pprev1.y + pw2.z*pprev1.z + pw2.w*pprev1.w;
            pprev0 = p0; pprev1 = p1;
            if (m0) { s0 = -1000.f; s2 = -1000.f; }
            if (m1) { s1 = -1000.f; s3 = -1000.f; }
            float e0 = __expf(s0), e1 = __expf(s1), e2 = __expf(s2), e3 = __expf(s3);
            acc[nt][0] = e0; acc[nt][1] = e1; acc[nt][2] = e2; acc[nt][3] = e3;
            ps1 += e0 + e1; ps2 += e2 + e3;
        }
        ps1 += __shfl_xor_sync(0xffffffffu, ps1, 1);
        ps1 += __shfl_xor_sync(0xffffffffu, ps1, 2);
        ps2 += __shfl_xor_sync(0xffffffffu, ps2, 1);
        ps2 += __shfl_xor_sync(0xffffffffu, ps2, 2);
        if ((lane & 3) == 0) {
            atomicAdd(&sums[g], ps1);
            atomicAdd(&sums[g + 8], ps2);
        }
    }
    __syncthreads();
    if (tid < 16) sums[tid] = 1.0f / sums[tid];
    __syncthreads();

    // ---- scale + direct sector-aligned stores (no staging) ----
    const float inv1 = sums[g];
    const float inv2 = sums[g + 8];
    float* ob1 = out + (((size_t)(h * B_SZ + b) * S_LEN + i0 + g) << 10) + jb + t2;
    float* ob2 = out + (((size_t)(h * B_SZ + b) * S_LEN + i0 + g + 8) << 10) + jb + t2;
    #pragma unroll
    for (int nt = 0; nt < 16; nt++) {
        *(float2*)(ob1 + nt * 8) = make_float2(acc[nt][0] * inv1, acc[nt][1] * inv1);
        *(float2*)(ob2 + nt * 8) = make_float2(acc[nt][2] * inv2, acc[nt][3] * inv2);
    }
}

// ---------------- launch ----------------
extern "C" void kernel_launch(void* const* d_in, const int* in_sizes, int n_in,
                              void* d_out, int out_size) {
    const float* x        = (const float*)d_in[0];
    const float* pos_emb  = (const float*)d_in[1];
    const unsigned char* kpm = (const unsigned char*)d_in[2];
    const float* in_w     = (const float*)d_in[3];
    const float* in_b     = (const float*)d_in[4];
    const float* lpw      = (const float*)d_in[5];
    float* out = (float*)d_out;

    {
        cudaFuncSetAttribute(pe_kernel,
                             cudaFuncAttributeMaxDynamicSharedMemorySize, PE_SMEM_BYTES);
        dim3 blk(32, 8);
        dim3 grd((NPE + PE_NB - 1) / PE_NB);
        pe_kernel<<<grd, blk, PE_SMEM_BYTES>>>(pos_emb, lpw);
    }
    {
        cudaFuncSetAttribute(proj_mma_kernel,
                             cudaFuncAttributeMaxDynamicSharedMemorySize, PJ_SMEM);
        dim3 grd((IN_PROJ + 63) / 64, 8192 / 256);
        proj_mma_kernel<<<grd, 256, PJ_SMEM>>>(x, in_w, in_b);
    }
    {
        cudaFuncSetAttribute(scores_kernel,
                             cudaFuncAttributeMaxDynamicSharedMemorySize, SC_SMEM);
        dim3 grd(S_LEN / 16, B_SZ, H_NUM);
        scores_kernel<<<grd, 256, SC_SMEM>>>(kpm, out);
    }
}